// round 13
// baseline (speedup 1.0000x reference)
#include <cuda_runtime.h>
#include <cuda_bf16.h>
#include <math.h>
#include <cstdint>

#define Bsz 1024
#define Kn  200
#define Dm  128
#define D2  256
#define G8  1024

typedef __nv_bfloat16 bf16;

__device__ __forceinline__ void split2(float x, bf16& h, bf16& l) {
    h = __float2bfloat16(x);
    l = __float2bfloat16(x - __bfloat162float(h));
}
__device__ __forceinline__ uint32_t pk2(bf16 a, bf16 b) {
    uint16_t ua = *(uint16_t*)&a, ub = *(uint16_t*)&b;
    return (uint32_t)ua | ((uint32_t)ub << 16);
}
__device__ __forceinline__ void splitp(float x0, float x1, uint32_t& hp, uint32_t& lp) {
    bf16 h0, l0, h1, l1;
    split2(x0, h0, l0); split2(x1, h1, l1);
    hp = pk2(h0, h1); lp = pk2(l0, l1);
}

__device__ __forceinline__ void mma16816(float* c, const uint32_t* a, const uint32_t* b) {
    asm volatile(
        "mma.sync.aligned.m16n8k16.row.col.f32.bf16.bf16.f32 "
        "{%0,%1,%2,%3}, {%4,%5,%6,%7}, {%8,%9}, {%0,%1,%2,%3};"
        : "+f"(c[0]), "+f"(c[1]), "+f"(c[2]), "+f"(c[3])
        : "r"(a[0]), "r"(a[1]), "r"(a[2]), "r"(a[3]), "r"(b[0]), "r"(b[1]));
}

#define CPA16(dst, src) \
    asm volatile("cp.async.cg.shared.global [%0], [%1], 16;" :: "r"(dst), "l"(src) : "memory")
#define CPA_COMMIT() asm volatile("cp.async.commit_group;" ::: "memory")
#define CPA_WAIT0()  asm volatile("cp.async.wait_group 0;" ::: "memory")

// ================= scratch =================
__device__ float g_qe[Bsz * Dm];
__device__ float g_sup[Bsz * Dm];
__device__ float g_sg[Bsz * Dm];
__device__ float g_sgn2[Bsz];
__device__ float g_qWb[Bsz * G8];
__device__ float g_scores[Bsz * Bsz];
__device__ float g_c[Bsz * D2];
__device__ float g_hout[Bsz * Dm];
__device__ float g_rp[8 * Bsz * Dm];
__device__ float g_bperm[G8];

__device__ bf16 g_scatA[Bsz * 768];
__device__ bf16 g_qeA[Bsz * 384];
__device__ bf16 g_supA[Bsz * 384];
__device__ bf16 g_hidA[Bsz * 768];
__device__ bf16 g_houtA[Bsz * 384];
__device__ bf16 g_hrA[Bsz * 768];
__device__ bf16 g_P[Bsz * 3072];
__device__ bf16 g_sgB[Bsz * 384];
__device__ bf16 g_sgT[Dm * 3072];
__device__ bf16 g_gcnB[Dm * 768];
__device__ bf16 g_p1B[D2 * 384];
__device__ bf16 g_p2B[Dm * 768];
__device__ bf16 g_wihB[G8 * 384];
__device__ bf16 g_whhB[G8 * 768];

// ================= fused weight conversion =================
__device__ __forceinline__ void convB_row(const float* src, bf16* dst, int srow,
                                          int drow, int K, int j) {
    if (j < K) {
        bf16 h, l; split2(src[(size_t)srow * K + j], h, l);
        bf16* d = dst + (size_t)drow * 3 * K;
        d[j] = h; d[K + j] = l; d[2 * K + j] = h;
    }
}
__global__ void conv_weights(const float* __restrict__ gcn_w, const float* __restrict__ p1_w,
                             const float* __restrict__ p2_w, const float* __restrict__ w_ih,
                             const float* __restrict__ w_hh, const float* __restrict__ b_ih,
                             const float* __restrict__ b_hh) {
    int blk = blockIdx.x, j = threadIdx.x;
    if (blk < 128) {
        convB_row(gcn_w, g_gcnB, blk, blk, 256, j);
    } else if (blk < 384) {
        convB_row(p1_w, g_p1B, blk - 128, blk - 128, 128, j);
    } else if (blk < 512) {
        convB_row(p2_w, g_p2B, blk - 384, blk - 384, 256, j);
    } else if (blk < 1536) {
        int n = blk - 512;
        convB_row(w_ih, g_wihB, n, (n & 255) * 4 + (n >> 8), 128, j);
    } else if (blk < 2560) {
        int n = blk - 1536;
        convB_row(w_hh, g_whhB, n, (n & 255) * 4 + (n >> 8), 256, j);
    } else {
        #pragma unroll
        for (int gidx = 0; gidx < 4; gidx++) {
            int n = gidx * 256 + j;
            g_bperm[j * 4 + gidx] = b_ih[n] + b_hh[n];
        }
    }
}

// ================= gather-sum =================
__global__ void gather_sum_kernel(const int* __restrict__ rel,
                                  const int* __restrict__ ent,
                                  const int* __restrict__ query,
                                  const float* __restrict__ emb) {
    __shared__ int sidx[2 * Kn];
    int b = blockIdx.x, d = threadIdx.x;
    for (int i = d; i < Kn; i += Dm) sidx[i] = rel[b * Kn + i];
    for (int i = d; i < Kn; i += Dm) sidx[Kn + i] = ent[b * Kn + i];
    __syncthreads();
    float ar = 0.f, ae = 0.f;
    #pragma unroll 8
    for (int k = 0; k < Kn; k++) ar += __ldg(&emb[(size_t)sidx[k] * Dm + d]);
    #pragma unroll 8
    for (int k = 0; k < Kn; k++) ae += __ldg(&emb[(size_t)sidx[Kn + k] * Dm + d]);
    bf16 h, l;
    bf16* sa = g_scatA + (size_t)b * 768;
    split2(ar, h, l); sa[d] = h; sa[256 + d] = h; sa[512 + d] = l;
    split2(ae, h, l); sa[128 + d] = h; sa[384 + d] = h; sa[640 + d] = l;
    float qv = emb[(size_t)query[b] * Dm + d];
    g_qe[b * Dm + d] = qv;
    bf16* qa = g_qeA + (size_t)b * 384;
    split2(qv, h, l); qa[d] = h; qa[128 + d] = h; qa[256 + d] = l;
}

// ================= bf16 mma GEMM, CTA tile 32x128, single-burst K-panel =========
// 8 warps, warp tile 32x16. Panel width BKW=384 loaded in ONE cp.async burst
// (30 x 16B per thread), then 24 k-steps of mma. klen/384 phases (1 or 2).
// MODE: 0 store; 1 SUP; 2 HID; 3 Z+LN; 4 QWB+LSTM1; 6 HH+LSTM
#define BKW 384
#define SMS 392
#define SMEM_DYN (160 * SMS * 2)
template <int MODE>
__global__ __launch_bounds__(256, 1)
void gemm_tc(const bf16* __restrict__ A, const bf16* __restrict__ B,
             float* __restrict__ C, int N, int K3, int klen,
             const float* __restrict__ b0, const float* __restrict__ b1,
             const float* __restrict__ b2) {
    extern __shared__ bf16 sm[];   // rows 0..31 = A tile, rows 32..159 = B tile
    __shared__ float rsum[32], rsq[32], rn2[32];
    int tid = threadIdx.x;
    int wid = tid >> 5, lane = tid & 31;
    int g = lane >> 2, t = lane & 3;
    int wn = wid;
    int nblk = blockIdx.x, mblk = blockIdx.y;
    int koff = blockIdx.z * klen;
    const bf16* Ab = A + (size_t)(mblk * 32) * K3 + koff;
    const bf16* Bb = B + (size_t)(nblk * 128) * K3 + koff;

    float acc[2][2][4];
    #pragma unroll
    for (int i = 0; i < 2; i++)
        #pragma unroll
        for (int j = 0; j < 2; j++)
            #pragma unroll
            for (int q = 0; q < 4; q++) acc[i][j][q] = 0.f;

    uint32_t smb;
    asm("{ .reg .u64 tt; cvta.to.shared.u64 tt, %1; cvt.u32.u64 %0, tt; }"
        : "=r"(smb) : "l"(sm));

    int nph = klen / BKW;
    for (int ph = 0; ph < nph; ph++) {
        if (ph > 0) __syncthreads();   // previous compute done reading smem
        int pho = ph * BKW;
        // one burst: 7680 16B transfers, 30 per thread
        #pragma unroll
        for (int i = 0; i < 30; i++) {
            int li = i * 256 + tid;      // 0..7679
            int row = li / 48;           // 0..159
            int c16 = li - row * 48;     // 0..47
            const bf16* src = (row < 32)
                ? (Ab + (size_t)row * K3 + pho + c16 * 8)
                : (Bb + (size_t)(row - 32) * K3 + pho + c16 * 8);
            CPA16(smb + (uint32_t)(row * (SMS * 2) + c16 * 16), src);
        }
        CPA_COMMIT();
        CPA_WAIT0();
        __syncthreads();
        // 24 k-steps
        for (int kk = 0; kk < 3; kk++) {
            #pragma unroll
            for (int k = 0; k < 8; k++) {
                int col = kk * 128 + k * 16 + 2 * t;
                uint32_t a[2][4], b[2][2];
                #pragma unroll
                for (int im = 0; im < 2; im++) {
                    int r = im * 16 + g;
                    a[im][0] = *(const uint32_t*)&sm[r * SMS + col];
                    a[im][1] = *(const uint32_t*)&sm[(r + 8) * SMS + col];
                    a[im][2] = *(const uint32_t*)&sm[r * SMS + col + 8];
                    a[im][3] = *(const uint32_t*)&sm[(r + 8) * SMS + col + 8];
                }
                #pragma unroll
                for (int jn = 0; jn < 2; jn++) {
                    int n = 32 + wn * 16 + jn * 8 + g;
                    b[jn][0] = *(const uint32_t*)&sm[n * SMS + col];
                    b[jn][1] = *(const uint32_t*)&sm[n * SMS + col + 8];
                }
                #pragma unroll
                for (int im = 0; im < 2; im++)
                    #pragma unroll
                    for (int jn = 0; jn < 2; jn++)
                        mma16816(acc[im][jn], a[im], b[jn]);
            }
        }
    }

    // ---------------- epilogues ----------------
    if constexpr (MODE == 0) {
        float* Cz = C + (size_t)blockIdx.z * 1024 * N;
        #pragma unroll
        for (int im = 0; im < 2; im++)
            #pragma unroll
            for (int jn = 0; jn < 2; jn++) {
                int r0 = mblk * 32 + im * 16 + g;
                int cb = nblk * 128 + wn * 16 + jn * 8 + 2 * t;
                *(float2*)&Cz[(size_t)r0 * N + cb] = make_float2(acc[im][jn][0], acc[im][jn][1]);
                *(float2*)&Cz[(size_t)(r0 + 8) * N + cb] = make_float2(acc[im][jn][2], acc[im][jn][3]);
            }
    } else if constexpr (MODE == 1) {
        #pragma unroll
        for (int im = 0; im < 2; im++)
            #pragma unroll
            for (int jn = 0; jn < 2; jn++) {
                int cb = wn * 16 + jn * 8 + 2 * t;
                float bb0 = 200.0f * __ldg(&b0[cb]), bb1 = 200.0f * __ldg(&b0[cb + 1]);
                #pragma unroll
                for (int pr = 0; pr < 2; pr++) {
                    int row = mblk * 32 + im * 16 + g + pr * 8;
                    float v0 = tanhf((acc[im][jn][2 * pr] + bb0) * (1.0f / 1024.0f));
                    float v1 = tanhf((acc[im][jn][2 * pr + 1] + bb1) * (1.0f / 1024.0f));
                    *(float2*)&g_sup[row * Dm + cb] = make_float2(v0, v1);
                    uint32_t hp, lp; splitp(v0, v1, hp, lp);
                    bf16* sa = g_supA + (size_t)row * 384;
                    *(uint32_t*)&sa[cb] = hp;
                    *(uint32_t*)&sa[128 + cb] = hp;
                    *(uint32_t*)&sa[256 + cb] = lp;
                }
            }
    } else if constexpr (MODE == 2) {
        #pragma unroll
        for (int im = 0; im < 2; im++)
            #pragma unroll
            for (int jn = 0; jn < 2; jn++) {
                int cb = nblk * 128 + wn * 16 + jn * 8 + 2 * t;
                float bb0 = __ldg(&b0[cb]), bb1 = __ldg(&b0[cb + 1]);
                #pragma unroll
                for (int pr = 0; pr < 2; pr++) {
                    int row = mblk * 32 + im * 16 + g + pr * 8;
                    float v0 = fmaxf(acc[im][jn][2 * pr] + bb0, 0.0f);
                    float v1 = fmaxf(acc[im][jn][2 * pr + 1] + bb1, 0.0f);
                    uint32_t hp, lp; splitp(v0, v1, hp, lp);
                    bf16* ha = g_hidA + (size_t)row * 768;
                    *(uint32_t*)&ha[cb] = hp;
                    *(uint32_t*)&ha[256 + cb] = hp;
                    *(uint32_t*)&ha[512 + cb] = lp;
                }
            }
    } else if constexpr (MODE == 3) {
        for (int i = tid; i < 32; i += 256) { rsum[i] = 0.f; rsq[i] = 0.f; rn2[i] = 0.f; }
        __syncthreads();
        #pragma unroll
        for (int im = 0; im < 2; im++) {
            float s0 = 0.f, s1 = 0.f, q0 = 0.f, q1 = 0.f;
            int ra = im * 16 + g;
            #pragma unroll
            for (int jn = 0; jn < 2; jn++) {
                int cb = wn * 16 + jn * 8 + 2 * t;
                float bb0 = __ldg(&b0[cb]), bb1 = __ldg(&b0[cb + 1]);
                int rowg0 = mblk * 32 + ra;
                float2 s0v = *(const float2*)&g_sup[rowg0 * Dm + cb];
                float2 s1v = *(const float2*)&g_sup[(rowg0 + 8) * Dm + cb];
                float z0 = acc[im][jn][0] + bb0 + s0v.x;
                float z1 = acc[im][jn][1] + bb1 + s0v.y;
                float z2 = acc[im][jn][2] + bb0 + s1v.x;
                float z3 = acc[im][jn][3] + bb1 + s1v.y;
                acc[im][jn][0] = z0; acc[im][jn][1] = z1;
                acc[im][jn][2] = z2; acc[im][jn][3] = z3;
                s0 += z0 + z1; q0 += z0 * z0 + z1 * z1;
                s1 += z2 + z3; q1 += z2 * z2 + z3 * z3;
            }
            atomicAdd(&rsum[ra], s0); atomicAdd(&rsq[ra], q0);
            atomicAdd(&rsum[ra + 8], s1); atomicAdd(&rsq[ra + 8], q1);
        }
        __syncthreads();
        #pragma unroll
        for (int im = 0; im < 2; im++) {
            int ra = im * 16 + g;
            float mu0 = rsum[ra] * (1.0f / 128.0f);
            float mu1 = rsum[ra + 8] * (1.0f / 128.0f);
            float sd0 = sqrtf(fmaxf((rsq[ra] - 128.0f * mu0 * mu0) * (1.0f / 127.0f), 0.f)) + 1e-3f;
            float sd1 = sqrtf(fmaxf((rsq[ra + 8] - 128.0f * mu1 * mu1) * (1.0f / 127.0f), 0.f)) + 1e-3f;
            float i0 = 1.0f / sd0, i1 = 1.0f / sd1;
            float n20 = 0.f, n21 = 0.f;
            #pragma unroll
            for (int jn = 0; jn < 2; jn++) {
                int cb = wn * 16 + jn * 8 + 2 * t;
                float la0 = __ldg(&b1[cb]), la1 = __ldg(&b1[cb + 1]);
                float lb0 = __ldg(&b2[cb]), lb1 = __ldg(&b2[cb + 1]);
                float sg0 = (acc[im][jn][0] - mu0) * i0 * la0 + lb0;
                float sg1 = (acc[im][jn][1] - mu0) * i0 * la1 + lb1;
                float sg2 = (acc[im][jn][2] - mu1) * i1 * la0 + lb0;
                float sg3 = (acc[im][jn][3] - mu1) * i1 * la1 + lb1;
                acc[im][jn][0] = sg0; acc[im][jn][1] = sg1;
                acc[im][jn][2] = sg2; acc[im][jn][3] = sg3;
                n20 += sg0 * sg0 + sg1 * sg1;
                n21 += sg2 * sg2 + sg3 * sg3;
            }
            atomicAdd(&rn2[ra], n20); atomicAdd(&rn2[ra + 8], n21);
        }
        __syncthreads();
        #pragma unroll
        for (int im = 0; im < 2; im++) {
            int ra = im * 16 + g;
            #pragma unroll
            for (int jn = 0; jn < 2; jn++) {
                int cb = wn * 16 + jn * 8 + 2 * t;
                #pragma unroll
                for (int pr = 0; pr < 2; pr++) {
                    int row = mblk * 32 + ra + pr * 8;
                    float v0 = acc[im][jn][2 * pr], v1 = acc[im][jn][2 * pr + 1];
                    *(float2*)&g_sg[row * Dm + cb] = make_float2(v0, v1);
                    uint32_t hp, lp; splitp(v0, v1, hp, lp);
                    bf16* sb = g_sgB + (size_t)row * 384;
                    *(uint32_t*)&sb[cb] = hp;
                    *(uint32_t*)&sb[128 + cb] = lp;
                    *(uint32_t*)&sb[256 + cb] = hp;
                    bf16 h0, l0, h1, l1;
                    split2(v0, h0, l0); split2(v1, h1, l1);
                    size_t tb0 = (size_t)cb * 3072 + (row >> 7) * 384 + (row & 127);
                    size_t tb1 = tb0 + 3072;
                    g_sgT[tb0] = h0; g_sgT[tb0 + 128] = l0; g_sgT[tb0 + 256] = h0;
                    g_sgT[tb1] = h1; g_sgT[tb1 + 128] = l1; g_sgT[tb1 + 256] = h1;
                }
            }
            if (wn == 0 && t == 0) {
                g_sgn2[mblk * 32 + ra] = rn2[ra];
                g_sgn2[mblk * 32 + ra + 8] = rn2[ra + 8];
            }
        }
    } else {
        constexpr int first = (MODE == 4);
        #pragma unroll
        for (int im = 0; im < 2; im++)
            #pragma unroll
            for (int jn = 0; jn < 2; jn++) {
                int r0 = mblk * 32 + im * 16 + g;
                int base8 = nblk * 128 + wn * 16 + jn * 8;
                int cb = base8 + 2 * t;
                float v0 = acc[im][jn][0], v1 = acc[im][jn][1];
                float v2 = acc[im][jn][2], v3 = acc[im][jn][3];
                if constexpr (first) {
                    float bb0 = __ldg(&g_bperm[cb]), bb1 = __ldg(&g_bperm[cb + 1]);
                    v0 += bb0; v1 += bb1; v2 += bb0; v3 += bb1;
                    *(float2*)&g_qWb[(size_t)r0 * G8 + cb] = make_float2(v0, v1);
                    *(float2*)&g_qWb[(size_t)(r0 + 8) * G8 + cb] = make_float2(v2, v3);
                } else {
                    float2 a0 = *(const float2*)&g_qWb[(size_t)r0 * G8 + cb];
                    float2 a1 = *(const float2*)&g_qWb[(size_t)(r0 + 8) * G8 + cb];
                    v0 += a0.x; v1 += a0.y; v2 += a1.x; v3 += a1.y;
                }
                float ex0 = __shfl_xor_sync(0xffffffffu, v0, 1);
                float ex1 = __shfl_xor_sync(0xffffffffu, v1, 1);
                float ex2 = __shfl_xor_sync(0xffffffffu, v2, 1);
                float ex3 = __shfl_xor_sync(0xffffffffu, v3, 1);
                float gi, gf, gg, go; int row;
                if ((t & 1) == 0) { gi = v0; gf = v1; gg = ex0; go = ex1; row = r0; }
                else             { gi = ex2; gf = ex3; gg = v2; go = v3; row = r0 + 8; }
                int j = (base8 >> 2) + (t >> 1);
                float cp = first ? 0.0f : g_c[row * D2 + j];
                float si = 1.0f / (1.0f + __expf(-gi));
                float sf = 1.0f / (1.0f + __expf(-gf));
                float so = 1.0f / (1.0f + __expf(-go));
                float cc = sf * cp + si * tanhf(gg);
                g_c[row * D2 + j] = cc;
                float h = so * tanhf(cc);
                if (j < Dm) {
                    float ho = g_qe[row * Dm + j] + h;
                    g_hout[row * Dm + j] = ho;
                    bf16 hh2, ll2; split2(ho, hh2, ll2);
                    bf16* ha = g_houtA + (size_t)row * 384;
                    ha[j] = hh2; ha[128 + j] = hh2; ha[256 + j] = ll2;
                    bf16* ra2 = g_hrA + (size_t)row * 768;
                    ra2[j] = hh2; ra2[256 + j] = hh2; ra2[512 + j] = ll2;
                }
            }
    }
}

// ================= softmax / reduce / cosine =================
__global__ void softmax_kernel() {
    __shared__ float s[8];
    int b = blockIdx.x, t = threadIdx.x;
    const float4* row = (const float4*)(g_scores + (size_t)b * Bsz);
    float4 x = row[t];
    float m = fmaxf(fmaxf(x.x, x.y), fmaxf(x.z, x.w));
    #pragma unroll
    for (int o = 16; o; o >>= 1) m = fmaxf(m, __shfl_xor_sync(0xffffffffu, m, o));
    if ((t & 31) == 0) s[t >> 5] = m;
    __syncthreads();
    m = fmaxf(fmaxf(fmaxf(s[0], s[1]), fmaxf(s[2], s[3])),
              fmaxf(fmaxf(s[4], s[5]), fmaxf(s[6], s[7])));
    __syncthreads();
    float e0 = __expf(x.x - m), e1 = __expf(x.y - m);
    float e2 = __expf(x.z - m), e3 = __expf(x.w - m);
    float l = e0 + e1 + e2 + e3;
    #pragma unroll
    for (int o = 16; o; o >>= 1) l += __shfl_xor_sync(0xffffffffu, l, o);
    if ((t & 31) == 0) s[t >> 5] = l;
    __syncthreads();
    l = s[0] + s[1] + s[2] + s[3] + s[4] + s[5] + s[6] + s[7];
    float inv = 1.0f / l;
    float p0 = e0 * inv, p1 = e1 * inv, p2 = e2 * inv, p3 = e3 * inv;
    int j0 = t * 4;
    int ks = j0 >> 7, jl0 = j0 & 127;
    bf16* base = g_P + (size_t)b * 3072 + ks * 384 + jl0;
    uint32_t hp0, lp0, hp1, lp1;
    splitp(p0, p1, hp0, lp0);
    splitp(p2, p3, hp1, lp1);
    ((uint32_t*)base)[0] = hp0; ((uint32_t*)base)[1] = hp1;
    ((uint32_t*)(base + 128))[0] = hp0; ((uint32_t*)(base + 128))[1] = hp1;
    ((uint32_t*)(base + 256))[0] = lp0; ((uint32_t*)(base + 256))[1] = lp1;
}

__global__ void reduce_r_kernel() {
    int b = blockIdx.x, d = threadIdx.x;
    float r = 0.f;
    #pragma unroll
    for (int z = 0; z < 8; z++) r += g_rp[(size_t)z * Bsz * Dm + b * Dm + d];
    bf16 h, l; split2(r, h, l);
    bf16* ra = g_hrA + (size_t)b * 768;
    ra[128 + d] = h; ra[384 + d] = h; ra[640 + d] = l;
}

__global__ void cosine_kernel(float* __restrict__ out) {
    __shared__ float s[4];
    int b = blockIdx.x, d = threadIdx.x;
    float ho = g_hout[b * Dm + d];
    float sg = g_sg[b * Dm + d];
    float cross = ho * sg, n1 = ho * ho;
    #pragma unroll
    for (int o = 16; o; o >>= 1) {
        cross += __shfl_xor_sync(0xffffffffu, cross, o);
        n1 += __shfl_xor_sync(0xffffffffu, n1, o);
    }
    if ((d & 31) == 0) { s[d >> 5] = cross; }
    __syncthreads();
    float cr = s[0] + s[1] + s[2] + s[3];
    __syncthreads();
    if ((d & 31) == 0) { s[d >> 5] = n1; }
    __syncthreads();
    float nn = s[0] + s[1] + s[2] + s[3];
    if (d == 0) out[b] = cr * rsqrtf(nn * g_sgn2[b]);
}

// ================= host orchestration =================
extern "C" void kernel_launch(void* const* d_in, const int* in_sizes, int n_in,
                              void* d_out, int out_size) {
    (void)in_sizes; (void)n_in; (void)out_size;
    const int*   relations = (const int*)d_in[0];
    const int*   entities  = (const int*)d_in[1];
    const int*   query     = (const int*)d_in[2];
    const float* emb       = (const float*)d_in[3];
    const float* gcn_w     = (const float*)d_in[4];
    const float* gcn_b     = (const float*)d_in[5];
    const float* p1_w      = (const float*)d_in[6];
    const float* p1_b      = (const float*)d_in[7];
    const float* p2_w      = (const float*)d_in[8];
    const float* p2_b      = (const float*)d_in[9];
    const float* ln_a      = (const float*)d_in[10];
    const float* ln_b      = (const float*)d_in[11];
    const float* w_ih      = (const float*)d_in[12];
    const float* w_hh      = (const float*)d_in[13];
    const float* b_ih      = (const float*)d_in[14];
    const float* b_hh      = (const float*)d_in[15];
    float* out = (float*)d_out;

    cudaFuncSetAttribute(gemm_tc<0>, cudaFuncAttributeMaxDynamicSharedMemorySize, SMEM_DYN);
    cudaFuncSetAttribute(gemm_tc<1>, cudaFuncAttributeMaxDynamicSharedMemorySize, SMEM_DYN);
    cudaFuncSetAttribute(gemm_tc<2>, cudaFuncAttributeMaxDynamicSharedMemorySize, SMEM_DYN);
    cudaFuncSetAttribute(gemm_tc<3>, cudaFuncAttributeMaxDynamicSharedMemorySize, SMEM_DYN);
    cudaFuncSetAttribute(gemm_tc<4>, cudaFuncAttributeMaxDynamicSharedMemorySize, SMEM_DYN);
    cudaFuncSetAttribute(gemm_tc<6>, cudaFuncAttributeMaxDynamicSharedMemorySize, SMEM_DYN);

    float *scores, *rp;
    bf16 *scatA, *qeA, *supA, *hidA, *houtA, *hrA, *P, *sgB, *sgT;
    bf16 *gcnB, *p1B, *p2B, *wihB, *whhB;
    cudaGetSymbolAddress((void**)&scores, g_scores);
    cudaGetSymbolAddress((void**)&rp, g_rp);
    cudaGetSymbolAddress((void**)&scatA, g_scatA);
    cudaGetSymbolAddress((void**)&qeA, g_qeA);
    cudaGetSymbolAddress((void**)&supA, g_supA);
    cudaGetSymbolAddress((void**)&hidA, g_hidA);
    cudaGetSymbolAddress((void**)&houtA, g_houtA);
    cudaGetSymbolAddress((void**)&hrA, g_hrA);
    cudaGetSymbolAddress((void**)&P, g_P);
    cudaGetSymbolAddress((void**)&sgB, g_sgB);
    cudaGetSymbolAddress((void**)&sgT, g_sgT);
    cudaGetSymbolAddress((void**)&gcnB, g_gcnB);
    cudaGetSymbolAddress((void**)&p1B, g_p1B);
    cudaGetSymbolAddress((void**)&p2B, g_p2B);
    cudaGetSymbolAddress((void**)&wihB, g_wihB);
    cudaGetSymbolAddress((void**)&whhB, g_whhB);

    // 1) weight conversions + bias permutation
    conv_weights<<<2561, 256>>>(gcn_w, p1_w, p2_w, w_ih, w_hh, b_ih, b_hh);
    // 2) gather + neighbor sums
    gather_sum_kernel<<<Bsz, Dm>>>(relations, entities, query, emb);
    // 3) sup = tanh((scat.gcn^T + 200b)/1024)
    gemm_tc<1><<<dim3(1, 32), 256, SMEM_DYN>>>(scatA, gcnB, nullptr, Dm, 768, 768,
                                               gcn_b, nullptr, nullptr);
    // 4) hidA = relu(sup.p1^T + b)
    gemm_tc<2><<<dim3(2, 32), 256, SMEM_DYN>>>(supA, p1B, nullptr, D2, 384, 384,
                                               p1_b, nullptr, nullptr);
    // 5) z = hid.p2^T + b + sup; fused layernorm
    gemm_tc<3><<<dim3(1, 32), 256, SMEM_DYN>>>(hidA, p2B, nullptr, Dm, 768, 768,
                                               p2_b, ln_a, ln_b);
    // 6) qWb + first LSTM step
    gemm_tc<4><<<dim3(8, 32), 256, SMEM_DYN>>>(qeA, wihB, nullptr, G8, 384, 384,
                                               nullptr, nullptr, nullptr);
    // 7) 3 attention+LSTM iterations
    for (int s = 1; s < 4; s++) {
        gemm_tc<0><<<dim3(8, 32), 256, SMEM_DYN>>>(houtA, sgB, scores, Bsz, 384, 384,
                                                   nullptr, nullptr, nullptr);
        softmax_kernel<<<Bsz, 256>>>();
        gemm_tc<0><<<dim3(1, 32, 8), 256, SMEM_DYN>>>(P, sgT, rp, Dm, 3072, 384,
                                                      nullptr, nullptr, nullptr);
        reduce_r_kernel<<<Bsz, Dm>>>();
        gemm_tc<6><<<dim3(8, 32), 256, SMEM_DYN>>>(hrA, whhB, nullptr, G8, 768, 768,
                                                   nullptr, nullptr, nullptr);
    }
    // 8) cosine
    cosine_kernel<<<Bsz, Dm>>>(out);
}

// round 14
// speedup vs baseline: 1.2033x; 1.2033x over previous
#include <cuda_runtime.h>
#include <cuda_bf16.h>
#include <math.h>
#include <cstdint>

#define Bsz 1024
#define Kn  200
#define Dm  128
#define D2  256
#define G8  1024

typedef __nv_bfloat16 bf16;

__device__ __forceinline__ void split2(float x, bf16& h, bf16& l) {
    h = __float2bfloat16(x);
    l = __float2bfloat16(x - __bfloat162float(h));
}
__device__ __forceinline__ uint32_t pk2(bf16 a, bf16 b) {
    uint16_t ua = *(uint16_t*)&a, ub = *(uint16_t*)&b;
    return (uint32_t)ua | ((uint32_t)ub << 16);
}
__device__ __forceinline__ void splitp(float x0, float x1, uint32_t& hp, uint32_t& lp) {
    bf16 h0, l0, h1, l1;
    split2(x0, h0, l0); split2(x1, h1, l1);
    hp = pk2(h0, h1); lp = pk2(l0, l1);
}

__device__ __forceinline__ void mma16816(float* c, const uint32_t* a, const uint32_t* b) {
    asm volatile(
        "mma.sync.aligned.m16n8k16.row.col.f32.bf16.bf16.f32 "
        "{%0,%1,%2,%3}, {%4,%5,%6,%7}, {%8,%9}, {%0,%1,%2,%3};"
        : "+f"(c[0]), "+f"(c[1]), "+f"(c[2]), "+f"(c[3])
        : "r"(a[0]), "r"(a[1]), "r"(a[2]), "r"(a[3]), "r"(b[0]), "r"(b[1]));
}

// ================= scratch =================
__device__ float g_qe[Bsz * Dm];
__device__ float g_sup[Bsz * Dm];
__device__ float g_sg[Bsz * Dm];
__device__ float g_sgn2[Bsz];
__device__ float g_qWb[Bsz * G8];
__device__ float g_scores[Bsz * Bsz];
__device__ float g_c[Bsz * D2];
__device__ float g_hout[Bsz * Dm];
__device__ float g_rp[8 * Bsz * Dm];
__device__ float g_bperm[G8];

__device__ bf16 g_scatA[Bsz * 768];
__device__ bf16 g_qeA[Bsz * 384];
__device__ bf16 g_supA[Bsz * 384];
__device__ bf16 g_hidA[Bsz * 768];
__device__ bf16 g_houtA[Bsz * 384];
__device__ bf16 g_hrA[Bsz * 768];
__device__ bf16 g_P[Bsz * 3072];
__device__ bf16 g_sgB[Bsz * 384];
__device__ bf16 g_sgT[Dm * 3072];
__device__ bf16 g_gcnB[Dm * 768];
__device__ bf16 g_p1B[D2 * 384];
__device__ bf16 g_p2B[Dm * 768];
__device__ bf16 g_wihB[G8 * 384];
__device__ bf16 g_whhB[G8 * 768];

// ================= fused weight conversion =================
__device__ __forceinline__ void convB_row(const float* src, bf16* dst, int srow,
                                          int drow, int K, int j) {
    if (j < K) {
        bf16 h, l; split2(src[(size_t)srow * K + j], h, l);
        bf16* d = dst + (size_t)drow * 3 * K;
        d[j] = h; d[K + j] = l; d[2 * K + j] = h;
    }
}
__global__ void conv_weights(const float* __restrict__ gcn_w, const float* __restrict__ p1_w,
                             const float* __restrict__ p2_w, const float* __restrict__ w_ih,
                             const float* __restrict__ w_hh, const float* __restrict__ b_ih,
                             const float* __restrict__ b_hh) {
    int blk = blockIdx.x, j = threadIdx.x;
    if (blk < 128) {
        convB_row(gcn_w, g_gcnB, blk, blk, 256, j);
    } else if (blk < 384) {
        convB_row(p1_w, g_p1B, blk - 128, blk - 128, 128, j);
    } else if (blk < 512) {
        convB_row(p2_w, g_p2B, blk - 384, blk - 384, 256, j);
    } else if (blk < 1536) {
        int n = blk - 512;
        convB_row(w_ih, g_wihB, n, (n & 255) * 4 + (n >> 8), 128, j);
    } else if (blk < 2560) {
        int n = blk - 1536;
        convB_row(w_hh, g_whhB, n, (n & 255) * 4 + (n >> 8), 256, j);
    } else {
        #pragma unroll
        for (int gidx = 0; gidx < 4; gidx++) {
            int n = gidx * 256 + j;
            g_bperm[j * 4 + gidx] = b_ih[n] + b_hh[n];
        }
    }
}

// ================= gather-sum =================
__global__ void gather_sum_kernel(const int* __restrict__ rel,
                                  const int* __restrict__ ent,
                                  const int* __restrict__ query,
                                  const float* __restrict__ emb) {
    __shared__ int sidx[2 * Kn];
    int b = blockIdx.x, d = threadIdx.x;
    for (int i = d; i < Kn; i += Dm) sidx[i] = rel[b * Kn + i];
    for (int i = d; i < Kn; i += Dm) sidx[Kn + i] = ent[b * Kn + i];
    __syncthreads();
    float ar = 0.f, ae = 0.f;
    #pragma unroll 8
    for (int k = 0; k < Kn; k++) ar += __ldg(&emb[(size_t)sidx[k] * Dm + d]);
    #pragma unroll 8
    for (int k = 0; k < Kn; k++) ae += __ldg(&emb[(size_t)sidx[Kn + k] * Dm + d]);
    bf16 h, l;
    bf16* sa = g_scatA + (size_t)b * 768;
    split2(ar, h, l); sa[d] = h; sa[256 + d] = h; sa[512 + d] = l;
    split2(ae, h, l); sa[128 + d] = h; sa[384 + d] = h; sa[640 + d] = l;
    float qv = emb[(size_t)query[b] * Dm + d];
    g_qe[b * Dm + d] = qv;
    bf16* qa = g_qeA + (size_t)b * 384;
    split2(qv, h, l); qa[d] = h; qa[128 + d] = h; qa[256 + d] = l;
}

// ================= bf16 mma GEMM, CTA tile MTx128, BK=128, double-buffered =====
// 8 warps, warp tile MTx16. MODE: 0 store; 1 SUP; 2 HID; 3 Z+LN; 4 QWB+LSTM1; 6 HH+LSTM
// MT = 32 (2 CTA/SM) for small grids, 64 (1 CTA/SM, one-wave grids) for big ones.
#define SMS 136
template <int MODE, int MT>
__global__ __launch_bounds__(256, (MT == 32) ? 2 : 1)
void gemm_tc(const bf16* __restrict__ A, const bf16* __restrict__ B,
             float* __restrict__ C, int N, int K3, int klen,
             const float* __restrict__ b0, const float* __restrict__ b1,
             const float* __restrict__ b2) {
    constexpr int IM = MT / 16;
    constexpr int STG = (MT + 128) * SMS;
    extern __shared__ bf16 sm[];
    __shared__ float rsum[32], rsq[32], rn2[32];
    int tid = threadIdx.x;
    int wid = tid >> 5, lane = tid & 31;
    int g = lane >> 2, t = lane & 3;
    int wn = wid;
    int nblk = blockIdx.x, mblk = blockIdx.y;
    int koff = blockIdx.z * klen;
    const bf16* Ab = A + (size_t)(mblk * MT) * K3 + koff;
    const bf16* Bb = B + (size_t)(nblk * 128) * K3 + koff;

    float acc[IM][2][4];
    #pragma unroll
    for (int i = 0; i < IM; i++)
        #pragma unroll
        for (int j = 0; j < 2; j++)
            #pragma unroll
            for (int q = 0; q < 4; q++) acc[i][j][q] = 0.f;

    int lr = tid >> 4;              // 0..15
    int lc = (tid & 15) * 8;        // 0..120
    int nch = klen >> 7;
    const bf16* Abase = Ab + (size_t)lr * K3 + lc;
    const bf16* Bbase = Bb + (size_t)lr * K3 + lc;
    size_t rs = (size_t)16 * K3;

    uint4 pa[IM], pb[8];
    #pragma unroll
    for (int i = 0; i < IM; i++) pa[i] = *(const uint4*)(Abase + i * rs);
    #pragma unroll
    for (int i = 0; i < 8; i++) pb[i] = *(const uint4*)(Bbase + i * rs);
    {
        bf16* Sd = sm;
        #pragma unroll
        for (int i = 0; i < IM; i++) *(uint4*)&Sd[(lr + 16 * i) * SMS + lc] = pa[i];
        bf16* Bd = sm + MT * SMS;
        #pragma unroll
        for (int i = 0; i < 8; i++) *(uint4*)&Bd[(lr + 16 * i) * SMS + lc] = pb[i];
    }
    if (nch > 1) {
        #pragma unroll
        for (int i = 0; i < IM; i++) pa[i] = *(const uint4*)(Abase + i * rs + 128);
        #pragma unroll
        for (int i = 0; i < 8; i++) pb[i] = *(const uint4*)(Bbase + i * rs + 128);
    }
    __syncthreads();

    for (int c = 0; c < nch; c++) {
        const bf16* As = sm + (c & 1) * STG;
        const bf16* Bs = As + MT * SMS;
        #pragma unroll
        for (int k = 0; k < 8; k++) {
            uint32_t a[IM][4], b[2][2];
            #pragma unroll
            for (int im = 0; im < IM; im++) {
                int r = im * 16 + g;
                a[im][0] = *(const uint32_t*)&As[r * SMS + k * 16 + 2 * t];
                a[im][1] = *(const uint32_t*)&As[(r + 8) * SMS + k * 16 + 2 * t];
                a[im][2] = *(const uint32_t*)&As[r * SMS + k * 16 + 2 * t + 8];
                a[im][3] = *(const uint32_t*)&As[(r + 8) * SMS + k * 16 + 2 * t + 8];
            }
            #pragma unroll
            for (int jn = 0; jn < 2; jn++) {
                int n = wn * 16 + jn * 8 + g;
                b[jn][0] = *(const uint32_t*)&Bs[n * SMS + k * 16 + 2 * t];
                b[jn][1] = *(const uint32_t*)&Bs[n * SMS + k * 16 + 2 * t + 8];
            }
            #pragma unroll
            for (int im = 0; im < IM; im++)
                #pragma unroll
                for (int jn = 0; jn < 2; jn++)
                    mma16816(acc[im][jn], a[im], b[jn]);
        }
        if (c + 1 < nch) {
            bf16* Sd = sm + ((c + 1) & 1) * STG;
            #pragma unroll
            for (int i = 0; i < IM; i++) *(uint4*)&Sd[(lr + 16 * i) * SMS + lc] = pa[i];
            bf16* Bd = Sd + MT * SMS;
            #pragma unroll
            for (int i = 0; i < 8; i++) *(uint4*)&Bd[(lr + 16 * i) * SMS + lc] = pb[i];
            if (c + 2 < nch) {
                int off = (c + 2) * 128;
                #pragma unroll
                for (int i = 0; i < IM; i++) pa[i] = *(const uint4*)(Abase + i * rs + off);
                #pragma unroll
                for (int i = 0; i < 8; i++) pb[i] = *(const uint4*)(Bbase + i * rs + off);
            }
            __syncthreads();
        }
    }

    // ---------------- epilogues ----------------
    if constexpr (MODE == 0) {
        float* Cz = C + (size_t)blockIdx.z * 1024 * N;
        #pragma unroll
        for (int im = 0; im < IM; im++)
            #pragma unroll
            for (int jn = 0; jn < 2; jn++) {
                int r0 = mblk * MT + im * 16 + g;
                int cb = nblk * 128 + wn * 16 + jn * 8 + 2 * t;
                *(float2*)&Cz[(size_t)r0 * N + cb] = make_float2(acc[im][jn][0], acc[im][jn][1]);
                *(float2*)&Cz[(size_t)(r0 + 8) * N + cb] = make_float2(acc[im][jn][2], acc[im][jn][3]);
            }
    } else if constexpr (MODE == 1) {
        #pragma unroll
        for (int im = 0; im < IM; im++)
            #pragma unroll
            for (int jn = 0; jn < 2; jn++) {
                int cb = wn * 16 + jn * 8 + 2 * t;
                float bb0 = 200.0f * __ldg(&b0[cb]), bb1 = 200.0f * __ldg(&b0[cb + 1]);
                #pragma unroll
                for (int pr = 0; pr < 2; pr++) {
                    int row = mblk * MT + im * 16 + g + pr * 8;
                    float v0 = tanhf((acc[im][jn][2 * pr] + bb0) * (1.0f / 1024.0f));
                    float v1 = tanhf((acc[im][jn][2 * pr + 1] + bb1) * (1.0f / 1024.0f));
                    *(float2*)&g_sup[row * Dm + cb] = make_float2(v0, v1);
                    uint32_t hp, lp; splitp(v0, v1, hp, lp);
                    bf16* sa = g_supA + (size_t)row * 384;
                    *(uint32_t*)&sa[cb] = hp;
                    *(uint32_t*)&sa[128 + cb] = hp;
                    *(uint32_t*)&sa[256 + cb] = lp;
                }
            }
    } else if constexpr (MODE == 2) {
        #pragma unroll
        for (int im = 0; im < IM; im++)
            #pragma unroll
            for (int jn = 0; jn < 2; jn++) {
                int cb = nblk * 128 + wn * 16 + jn * 8 + 2 * t;
                float bb0 = __ldg(&b0[cb]), bb1 = __ldg(&b0[cb + 1]);
                #pragma unroll
                for (int pr = 0; pr < 2; pr++) {
                    int row = mblk * MT + im * 16 + g + pr * 8;
                    float v0 = fmaxf(acc[im][jn][2 * pr] + bb0, 0.0f);
                    float v1 = fmaxf(acc[im][jn][2 * pr + 1] + bb1, 0.0f);
                    uint32_t hp, lp; splitp(v0, v1, hp, lp);
                    bf16* ha = g_hidA + (size_t)row * 768;
                    *(uint32_t*)&ha[cb] = hp;
                    *(uint32_t*)&ha[256 + cb] = hp;
                    *(uint32_t*)&ha[512 + cb] = lp;
                }
            }
    } else if constexpr (MODE == 3) {   // MT must be 32 here (reduction arrays)
        for (int i = tid; i < 32; i += 256) { rsum[i] = 0.f; rsq[i] = 0.f; rn2[i] = 0.f; }
        __syncthreads();
        #pragma unroll
        for (int im = 0; im < IM; im++) {
            float s0 = 0.f, s1 = 0.f, q0 = 0.f, q1 = 0.f;
            int ra = im * 16 + g;
            #pragma unroll
            for (int jn = 0; jn < 2; jn++) {
                int cb = wn * 16 + jn * 8 + 2 * t;
                float bb0 = __ldg(&b0[cb]), bb1 = __ldg(&b0[cb + 1]);
                int rowg0 = mblk * MT + ra;
                float2 s0v = *(const float2*)&g_sup[rowg0 * Dm + cb];
                float2 s1v = *(const float2*)&g_sup[(rowg0 + 8) * Dm + cb];
                float z0 = acc[im][jn][0] + bb0 + s0v.x;
                float z1 = acc[im][jn][1] + bb1 + s0v.y;
                float z2 = acc[im][jn][2] + bb0 + s1v.x;
                float z3 = acc[im][jn][3] + bb1 + s1v.y;
                acc[im][jn][0] = z0; acc[im][jn][1] = z1;
                acc[im][jn][2] = z2; acc[im][jn][3] = z3;
                s0 += z0 + z1; q0 += z0 * z0 + z1 * z1;
                s1 += z2 + z3; q1 += z2 * z2 + z3 * z3;
            }
            atomicAdd(&rsum[ra], s0); atomicAdd(&rsq[ra], q0);
            atomicAdd(&rsum[ra + 8], s1); atomicAdd(&rsq[ra + 8], q1);
        }
        __syncthreads();
        #pragma unroll
        for (int im = 0; im < IM; im++) {
            int ra = im * 16 + g;
            float mu0 = rsum[ra] * (1.0f / 128.0f);
            float mu1 = rsum[ra + 8] * (1.0f / 128.0f);
            float sd0 = sqrtf(fmaxf((rsq[ra] - 128.0f * mu0 * mu0) * (1.0f / 127.0f), 0.f)) + 1e-3f;
            float sd1 = sqrtf(fmaxf((rsq[ra + 8] - 128.0f * mu1 * mu1) * (1.0f / 127.0f), 0.f)) + 1e-3f;
            float i0 = 1.0f / sd0, i1 = 1.0f / sd1;
            float n20 = 0.f, n21 = 0.f;
            #pragma unroll
            for (int jn = 0; jn < 2; jn++) {
                int cb = wn * 16 + jn * 8 + 2 * t;
                float la0 = __ldg(&b1[cb]), la1 = __ldg(&b1[cb + 1]);
                float lb0 = __ldg(&b2[cb]), lb1 = __ldg(&b2[cb + 1]);
                float sg0 = (acc[im][jn][0] - mu0) * i0 * la0 + lb0;
                float sg1 = (acc[im][jn][1] - mu0) * i0 * la1 + lb1;
                float sg2 = (acc[im][jn][2] - mu1) * i1 * la0 + lb0;
                float sg3 = (acc[im][jn][3] - mu1) * i1 * la1 + lb1;
                acc[im][jn][0] = sg0; acc[im][jn][1] = sg1;
                acc[im][jn][2] = sg2; acc[im][jn][3] = sg3;
                n20 += sg0 * sg0 + sg1 * sg1;
                n21 += sg2 * sg2 + sg3 * sg3;
            }
            atomicAdd(&rn2[ra], n20); atomicAdd(&rn2[ra + 8], n21);
        }
        __syncthreads();
        #pragma unroll
        for (int im = 0; im < IM; im++) {
            int ra = im * 16 + g;
            #pragma unroll
            for (int jn = 0; jn < 2; jn++) {
                int cb = wn * 16 + jn * 8 + 2 * t;
                #pragma unroll
                for (int pr = 0; pr < 2; pr++) {
                    int row = mblk * MT + ra + pr * 8;
                    float v0 = acc[im][jn][2 * pr], v1 = acc[im][jn][2 * pr + 1];
                    *(float2*)&g_sg[row * Dm + cb] = make_float2(v0, v1);
                    uint32_t hp, lp; splitp(v0, v1, hp, lp);
                    bf16* sb = g_sgB + (size_t)row * 384;
                    *(uint32_t*)&sb[cb] = hp;
                    *(uint32_t*)&sb[128 + cb] = lp;
                    *(uint32_t*)&sb[256 + cb] = hp;
                    bf16 h0, l0, h1, l1;
                    split2(v0, h0, l0); split2(v1, h1, l1);
                    size_t tb0 = (size_t)cb * 3072 + (row >> 7) * 384 + (row & 127);
                    size_t tb1 = tb0 + 3072;
                    g_sgT[tb0] = h0; g_sgT[tb0 + 128] = l0; g_sgT[tb0 + 256] = h0;
                    g_sgT[tb1] = h1; g_sgT[tb1 + 128] = l1; g_sgT[tb1 + 256] = h1;
                }
            }
            if (wn == 0 && t == 0) {
                g_sgn2[mblk * MT + ra] = rn2[ra];
                g_sgn2[mblk * MT + ra + 8] = rn2[ra + 8];
            }
        }
    } else {
        constexpr int first = (MODE == 4);
        #pragma unroll
        for (int im = 0; im < IM; im++)
            #pragma unroll
            for (int jn = 0; jn < 2; jn++) {
                int r0 = mblk * MT + im * 16 + g;
                int base8 = nblk * 128 + wn * 16 + jn * 8;
                int cb = base8 + 2 * t;
                float v0 = acc[im][jn][0], v1 = acc[im][jn][1];
                float v2 = acc[im][jn][2], v3 = acc[im][jn][3];
                if constexpr (first) {
                    float bb0 = __ldg(&g_bperm[cb]), bb1 = __ldg(&g_bperm[cb + 1]);
                    v0 += bb0; v1 += bb1; v2 += bb0; v3 += bb1;
                    *(float2*)&g_qWb[(size_t)r0 * G8 + cb] = make_float2(v0, v1);
                    *(float2*)&g_qWb[(size_t)(r0 + 8) * G8 + cb] = make_float2(v2, v3);
                } else {
                    float2 a0 = *(const float2*)&g_qWb[(size_t)r0 * G8 + cb];
                    float2 a1 = *(const float2*)&g_qWb[(size_t)(r0 + 8) * G8 + cb];
                    v0 += a0.x; v1 += a0.y; v2 += a1.x; v3 += a1.y;
                }
                float ex0 = __shfl_xor_sync(0xffffffffu, v0, 1);
                float ex1 = __shfl_xor_sync(0xffffffffu, v1, 1);
                float ex2 = __shfl_xor_sync(0xffffffffu, v2, 1);
                float ex3 = __shfl_xor_sync(0xffffffffu, v3, 1);
                float gi, gf, gg, go; int row;
                if ((t & 1) == 0) { gi = v0; gf = v1; gg = ex0; go = ex1; row = r0; }
                else             { gi = ex2; gf = ex3; gg = v2; go = v3; row = r0 + 8; }
                int j = (base8 >> 2) + (t >> 1);
                float cp = first ? 0.0f : g_c[row * D2 + j];
                float si = 1.0f / (1.0f + __expf(-gi));
                float sf = 1.0f / (1.0f + __expf(-gf));
                float so = 1.0f / (1.0f + __expf(-go));
                float cc = sf * cp + si * tanhf(gg);
                g_c[row * D2 + j] = cc;
                float h = so * tanhf(cc);
                if (j < Dm) {
                    float ho = g_qe[row * Dm + j] + h;
                    g_hout[row * Dm + j] = ho;
                    bf16 hh2, ll2; split2(ho, hh2, ll2);
                    bf16* ha = g_houtA + (size_t)row * 384;
                    ha[j] = hh2; ha[128 + j] = hh2; ha[256 + j] = ll2;
                    bf16* ra2 = g_hrA + (size_t)row * 768;
                    ra2[j] = hh2; ra2[256 + j] = hh2; ra2[512 + j] = ll2;
                }
            }
    }
}

// ================= softmax / reduce / cosine =================
__global__ void softmax_kernel() {
    __shared__ float s[8];
    int b = blockIdx.x, t = threadIdx.x;
    const float4* row = (const float4*)(g_scores + (size_t)b * Bsz);
    float4 x = row[t];
    float m = fmaxf(fmaxf(x.x, x.y), fmaxf(x.z, x.w));
    #pragma unroll
    for (int o = 16; o; o >>= 1) m = fmaxf(m, __shfl_xor_sync(0xffffffffu, m, o));
    if ((t & 31) == 0) s[t >> 5] = m;
    __syncthreads();
    m = fmaxf(fmaxf(fmaxf(s[0], s[1]), fmaxf(s[2], s[3])),
              fmaxf(fmaxf(s[4], s[5]), fmaxf(s[6], s[7])));
    __syncthreads();
    float e0 = __expf(x.x - m), e1 = __expf(x.y - m);
    float e2 = __expf(x.z - m), e3 = __expf(x.w - m);
    float l = e0 + e1 + e2 + e3;
    #pragma unroll
    for (int o = 16; o; o >>= 1) l += __shfl_xor_sync(0xffffffffu, l, o);
    if ((t & 31) == 0) s[t >> 5] = l;
    __syncthreads();
    l = s[0] + s[1] + s[2] + s[3] + s[4] + s[5] + s[6] + s[7];
    float inv = 1.0f / l;
    float p0 = e0 * inv, p1 = e1 * inv, p2 = e2 * inv, p3 = e3 * inv;
    int j0 = t * 4;
    int ks = j0 >> 7, jl0 = j0 & 127;
    bf16* base = g_P + (size_t)b * 3072 + ks * 384 + jl0;
    uint32_t hp0, lp0, hp1, lp1;
    splitp(p0, p1, hp0, lp0);
    splitp(p2, p3, hp1, lp1);
    ((uint32_t*)base)[0] = hp0; ((uint32_t*)base)[1] = hp1;
    ((uint32_t*)(base + 128))[0] = hp0; ((uint32_t*)(base + 128))[1] = hp1;
    ((uint32_t*)(base + 256))[0] = lp0; ((uint32_t*)(base + 256))[1] = lp1;
}

__global__ void reduce_r_kernel() {
    int b = blockIdx.x, d = threadIdx.x;
    float r = 0.f;
    #pragma unroll
    for (int z = 0; z < 8; z++) r += g_rp[(size_t)z * Bsz * Dm + b * Dm + d];
    bf16 h, l; split2(r, h, l);
    bf16* ra = g_hrA + (size_t)b * 768;
    ra[128 + d] = h; ra[384 + d] = h; ra[640 + d] = l;
}

__global__ void cosine_kernel(float* __restrict__ out) {
    __shared__ float s[4];
    int b = blockIdx.x, d = threadIdx.x;
    float ho = g_hout[b * Dm + d];
    float sg = g_sg[b * Dm + d];
    float cross = ho * sg, n1 = ho * ho;
    #pragma unroll
    for (int o = 16; o; o >>= 1) {
        cross += __shfl_xor_sync(0xffffffffu, cross, o);
        n1 += __shfl_xor_sync(0xffffffffu, n1, o);
    }
    if ((d & 31) == 0) { s[d >> 5] = cross; }
    __syncthreads();
    float cr = s[0] + s[1] + s[2] + s[3];
    __syncthreads();
    if ((d & 31) == 0) { s[d >> 5] = n1; }
    __syncthreads();
    float nn = s[0] + s[1] + s[2] + s[3];
    if (d == 0) out[b] = cr * rsqrtf(nn * g_sgn2[b]);
}

// ================= host orchestration =================
#define SM32 (2 * (160 * SMS) * 2)
#define SM64 (2 * (192 * SMS) * 2)
extern "C" void kernel_launch(void* const* d_in, const int* in_sizes, int n_in,
                              void* d_out, int out_size) {
    (void)in_sizes; (void)n_in; (void)out_size;
    const int*   relations = (const int*)d_in[0];
    const int*   entities  = (const int*)d_in[1];
    const int*   query     = (const int*)d_in[2];
    const float* emb       = (const float*)d_in[3];
    const float* gcn_w     = (const float*)d_in[4];
    const float* gcn_b     = (const float*)d_in[5];
    const float* p1_w      = (const float*)d_in[6];
    const float* p1_b      = (const float*)d_in[7];
    const float* p2_w      = (const float*)d_in[8];
    const float* p2_b      = (const float*)d_in[9];
    const float* ln_a      = (const float*)d_in[10];
    const float* ln_b      = (const float*)d_in[11];
    const float* w_ih      = (const float*)d_in[12];
    const float* w_hh      = (const float*)d_in[13];
    const float* b_ih      = (const float*)d_in[14];
    const float* b_hh      = (const float*)d_in[15];
    float* out = (float*)d_out;

    cudaFuncSetAttribute(gemm_tc<0, 64>, cudaFuncAttributeMaxDynamicSharedMemorySize, SM64);
    cudaFuncSetAttribute(gemm_tc<1, 32>, cudaFuncAttributeMaxDynamicSharedMemorySize, SM32);
    cudaFuncSetAttribute(gemm_tc<2, 32>, cudaFuncAttributeMaxDynamicSharedMemorySize, SM32);
    cudaFuncSetAttribute(gemm_tc<3, 32>, cudaFuncAttributeMaxDynamicSharedMemorySize, SM32);
    cudaFuncSetAttribute(gemm_tc<4, 64>, cudaFuncAttributeMaxDynamicSharedMemorySize, SM64);
    cudaFuncSetAttribute(gemm_tc<6, 64>, cudaFuncAttributeMaxDynamicSharedMemorySize, SM64);

    float *scores, *rp;
    bf16 *scatA, *qeA, *supA, *hidA, *houtA, *hrA, *P, *sgB, *sgT;
    bf16 *gcnB, *p1B, *p2B, *wihB, *whhB;
    cudaGetSymbolAddress((void**)&scores, g_scores);
    cudaGetSymbolAddress((void**)&rp, g_rp);
    cudaGetSymbolAddress((void**)&scatA, g_scatA);
    cudaGetSymbolAddress((void**)&qeA, g_qeA);
    cudaGetSymbolAddress((void**)&supA, g_supA);
    cudaGetSymbolAddress((void**)&hidA, g_hidA);
    cudaGetSymbolAddress((void**)&houtA, g_houtA);
    cudaGetSymbolAddress((void**)&hrA, g_hrA);
    cudaGetSymbolAddress((void**)&P, g_P);
    cudaGetSymbolAddress((void**)&sgB, g_sgB);
    cudaGetSymbolAddress((void**)&sgT, g_sgT);
    cudaGetSymbolAddress((void**)&gcnB, g_gcnB);
    cudaGetSymbolAddress((void**)&p1B, g_p1B);
    cudaGetSymbolAddress((void**)&p2B, g_p2B);
    cudaGetSymbolAddress((void**)&wihB, g_wihB);
    cudaGetSymbolAddress((void**)&whhB, g_whhB);

    // 1) weight conversions + bias permutation
    conv_weights<<<2561, 256>>>(gcn_w, p1_w, p2_w, w_ih, w_hh, b_ih, b_hh);
    // 2) gather + neighbor sums
    gather_sum_kernel<<<Bsz, Dm>>>(relations, entities, query, emb);
    // 3) sup = tanh((scat.gcn^T + 200b)/1024)
    gemm_tc<1, 32><<<dim3(1, 32), 256, SM32>>>(scatA, gcnB, nullptr, Dm, 768, 768,
                                               gcn_b, nullptr, nullptr);
    // 4) hidA = relu(sup.p1^T + b)
    gemm_tc<2, 32><<<dim3(2, 32), 256, SM32>>>(supA, p1B, nullptr, D2, 384, 384,
                                               p1_b, nullptr, nullptr);
    // 5) z = hid.p2^T + b + sup; fused layernorm
    gemm_tc<3, 32><<<dim3(1, 32), 256, SM32>>>(hidA, p2B, nullptr, Dm, 768, 768,
                                               p2_b, ln_a, ln_b);
    // 6) qWb + first LSTM step (one-wave MT=64 grid)
    gemm_tc<4, 64><<<dim3(8, 16), 256, SM64>>>(qeA, wihB, nullptr, G8, 384, 384,
                                               nullptr, nullptr, nullptr);
    // 7) 3 attention+LSTM iterations
    for (int s = 1; s < 4; s++) {
        gemm_tc<0, 64><<<dim3(8, 16), 256, SM64>>>(houtA, sgB, scores, Bsz, 384, 384,
                                                   nullptr, nullptr, nullptr);
        softmax_kernel<<<Bsz, 256>>>();
        gemm_tc<0, 64><<<dim3(1, 16, 8), 256, SM64>>>(P, sgT, rp, Dm, 3072, 384,
                                                      nullptr, nullptr, nullptr);
        reduce_r_kernel<<<Bsz, Dm>>>();
        gemm_tc<6, 64><<<dim3(8, 16), 256, SM64>>>(hrA, whhB, nullptr, G8, 768, 768,
                                                   nullptr, nullptr, nullptr);
    }
    // 8) cosine
    cosine_kernel<<<Bsz, Dm>>>(out);
}

// round 15
// speedup vs baseline: 1.2615x; 1.0484x over previous
#include <cuda_runtime.h>
#include <cuda_bf16.h>
#include <math.h>
#include <cstdint>

#define Bsz 1024
#define Kn  200
#define Dm  128
#define D2  256
#define G8  1024

typedef __nv_bfloat16 bf16;

__device__ __forceinline__ void split2(float x, bf16& h, bf16& l) {
    h = __float2bfloat16(x);
    l = __float2bfloat16(x - __bfloat162float(h));
}
__device__ __forceinline__ uint32_t pk2(bf16 a, bf16 b) {
    uint16_t ua = *(uint16_t*)&a, ub = *(uint16_t*)&b;
    return (uint32_t)ua | ((uint32_t)ub << 16);
}
__device__ __forceinline__ void splitp(float x0, float x1, uint32_t& hp, uint32_t& lp) {
    bf16 h0, l0, h1, l1;
    split2(x0, h0, l0); split2(x1, h1, l1);
    hp = pk2(h0, h1); lp = pk2(l0, l1);
}

__device__ __forceinline__ void mma16816(float* c, const uint32_t* a, const uint32_t* b) {
    asm volatile(
        "mma.sync.aligned.m16n8k16.row.col.f32.bf16.bf16.f32 "
        "{%0,%1,%2,%3}, {%4,%5,%6,%7}, {%8,%9}, {%0,%1,%2,%3};"
        : "+f"(c[0]), "+f"(c[1]), "+f"(c[2]), "+f"(c[3])
        : "r"(a[0]), "r"(a[1]), "r"(a[2]), "r"(a[3]), "r"(b[0]), "r"(b[1]));
}

// ================= scratch =================
__device__ float g_qe[Bsz * Dm];
__device__ float g_sup[Bsz * Dm];
__device__ float g_sg[Bsz * Dm];
__device__ float g_sgn2[Bsz];
__device__ float g_qWb[Bsz * G8];
__device__ float g_scores[Bsz * Bsz];
__device__ float g_c[Bsz * D2];
__device__ float g_hout[Bsz * Dm];
__device__ float g_rp[8 * Bsz * Dm];
__device__ float g_bperm[G8];

__device__ bf16 g_scatA[Bsz * 768];
__device__ bf16 g_qeA[Bsz * 384];
__device__ bf16 g_supA[Bsz * 384];
__device__ bf16 g_hidA[Bsz * 768];
__device__ bf16 g_houtA[Bsz * 384];
__device__ bf16 g_hrA[Bsz * 768];
__device__ bf16 g_P[Bsz * 3072];
__device__ bf16 g_sgB[Bsz * 384];
__device__ bf16 g_sgT[Dm * 3072];
__device__ bf16 g_gcnB[Dm * 768];
__device__ bf16 g_p1B[D2 * 384];
__device__ bf16 g_p2B[Dm * 768];
__device__ bf16 g_wihB[G8 * 384];
__device__ bf16 g_whhB[G8 * 768];

// ================= fused front: weight conversion + gather-sum =================
__device__ __forceinline__ void convB_row(const float* src, bf16* dst, int srow,
                                          int drow, int K, int j) {
    if (j < K) {
        bf16 h, l; split2(src[(size_t)srow * K + j], h, l);
        bf16* d = dst + (size_t)drow * 3 * K;
        d[j] = h; d[K + j] = l; d[2 * K + j] = h;
    }
}
__global__ void front_kernel(const float* __restrict__ gcn_w, const float* __restrict__ p1_w,
                             const float* __restrict__ p2_w, const float* __restrict__ w_ih,
                             const float* __restrict__ w_hh, const float* __restrict__ b_ih,
                             const float* __restrict__ b_hh,
                             const int* __restrict__ rel, const int* __restrict__ ent,
                             const int* __restrict__ query, const float* __restrict__ emb) {
    int blk = blockIdx.x, j = threadIdx.x;
    if (blk < 128) {
        convB_row(gcn_w, g_gcnB, blk, blk, 256, j);
    } else if (blk < 384) {
        convB_row(p1_w, g_p1B, blk - 128, blk - 128, 128, j);
    } else if (blk < 512) {
        convB_row(p2_w, g_p2B, blk - 384, blk - 384, 256, j);
    } else if (blk < 1536) {
        int n = blk - 512;
        convB_row(w_ih, g_wihB, n, (n & 255) * 4 + (n >> 8), 128, j);
    } else if (blk < 2560) {
        int n = blk - 1536;
        convB_row(w_hh, g_whhB, n, (n & 255) * 4 + (n >> 8), 256, j);
    } else if (blk == 2560) {
        #pragma unroll
        for (int gidx = 0; gidx < 4; gidx++) {
            int n = gidx * 256 + j;
            g_bperm[j * 4 + gidx] = b_ih[n] + b_hh[n];
        }
    } else {
        // gather-sum for batch row b; warps 0-3: rel sum, warps 4-7: ent sum
        __shared__ int sidx[2 * Kn];
        int b = blk - 2561;
        int half = j >> 7;          // 0 rel, 1 ent
        int d = j & 127;
        if (half == 0) {
            for (int i = d; i < Kn; i += 128) sidx[i] = rel[b * Kn + i];
        } else {
            for (int i = d; i < Kn; i += 128) sidx[Kn + i] = ent[b * Kn + i];
        }
        __syncthreads();
        const int* idx = sidx + half * Kn;
        float a = 0.f;
        #pragma unroll 8
        for (int k = 0; k < Kn; k++) a += __ldg(&emb[(size_t)idx[k] * Dm + d]);
        bf16 h, l;
        bf16* sa = g_scatA + (size_t)b * 768;   // K=256, A layout [h|h|l]
        split2(a, h, l);
        if (half == 0) { sa[d] = h; sa[256 + d] = h; sa[512 + d] = l; }
        else           { sa[128 + d] = h; sa[384 + d] = h; sa[640 + d] = l; }
        if (half == 0) {
            float qv = emb[(size_t)query[b] * Dm + d];
            g_qe[b * Dm + d] = qv;
            bf16* qa = g_qeA + (size_t)b * 384;
            split2(qv, h, l); qa[d] = h; qa[128 + d] = h; qa[256 + d] = l;
        }
    }
}

// ================= bf16 mma GEMM, CTA tile MTx128, BK=128, double-buffered =====
// 8 warps, warp tile MTx16. MODE: 0 store; 1 SUP; 2 HID; 3 Z+LN; 4 QWB+LSTM1; 6 HH+LSTM
#define SMS 136
template <int MODE, int MT>
__global__ __launch_bounds__(256, (MT == 32) ? 2 : 1)
void gemm_tc(const bf16* __restrict__ A, const bf16* __restrict__ B,
             float* __restrict__ C, int N, int K3, int klen,
             const float* __restrict__ b0, const float* __restrict__ b1,
             const float* __restrict__ b2) {
    constexpr int IM = MT / 16;
    constexpr int STG = (MT + 128) * SMS;
    extern __shared__ bf16 sm[];
    __shared__ float rsum[32], rsq[32], rn2[32];
    int tid = threadIdx.x;
    int wid = tid >> 5, lane = tid & 31;
    int g = lane >> 2, t = lane & 3;
    int wn = wid;
    int nblk = blockIdx.x, mblk = blockIdx.y;
    int koff = blockIdx.z * klen;
    const bf16* Ab = A + (size_t)(mblk * MT) * K3 + koff;
    const bf16* Bb = B + (size_t)(nblk * 128) * K3 + koff;

    float acc[IM][2][4];
    #pragma unroll
    for (int i = 0; i < IM; i++)
        #pragma unroll
        for (int j = 0; j < 2; j++)
            #pragma unroll
            for (int q = 0; q < 4; q++) acc[i][j][q] = 0.f;

    int lr = tid >> 4;
    int lc = (tid & 15) * 8;
    int nch = klen >> 7;
    const bf16* Abase = Ab + (size_t)lr * K3 + lc;
    const bf16* Bbase = Bb + (size_t)lr * K3 + lc;
    size_t rs = (size_t)16 * K3;

    uint4 pa[IM], pb[8];
    #pragma unroll
    for (int i = 0; i < IM; i++) pa[i] = *(const uint4*)(Abase + i * rs);
    #pragma unroll
    for (int i = 0; i < 8; i++) pb[i] = *(const uint4*)(Bbase + i * rs);
    {
        bf16* Sd = sm;
        #pragma unroll
        for (int i = 0; i < IM; i++) *(uint4*)&Sd[(lr + 16 * i) * SMS + lc] = pa[i];
        bf16* Bd = sm + MT * SMS;
        #pragma unroll
        for (int i = 0; i < 8; i++) *(uint4*)&Bd[(lr + 16 * i) * SMS + lc] = pb[i];
    }
    if (nch > 1) {
        #pragma unroll
        for (int i = 0; i < IM; i++) pa[i] = *(const uint4*)(Abase + i * rs + 128);
        #pragma unroll
        for (int i = 0; i < 8; i++) pb[i] = *(const uint4*)(Bbase + i * rs + 128);
    }
    __syncthreads();

    for (int c = 0; c < nch; c++) {
        const bf16* As = sm + (c & 1) * STG;
        const bf16* Bs = As + MT * SMS;
        #pragma unroll
        for (int k = 0; k < 8; k++) {
            uint32_t a[IM][4], b[2][2];
            #pragma unroll
            for (int im = 0; im < IM; im++) {
                int r = im * 16 + g;
                a[im][0] = *(const uint32_t*)&As[r * SMS + k * 16 + 2 * t];
                a[im][1] = *(const uint32_t*)&As[(r + 8) * SMS + k * 16 + 2 * t];
                a[im][2] = *(const uint32_t*)&As[r * SMS + k * 16 + 2 * t + 8];
                a[im][3] = *(const uint32_t*)&As[(r + 8) * SMS + k * 16 + 2 * t + 8];
            }
            #pragma unroll
            for (int jn = 0; jn < 2; jn++) {
                int n = wn * 16 + jn * 8 + g;
                b[jn][0] = *(const uint32_t*)&Bs[n * SMS + k * 16 + 2 * t];
                b[jn][1] = *(const uint32_t*)&Bs[n * SMS + k * 16 + 2 * t + 8];
            }
            #pragma unroll
            for (int im = 0; im < IM; im++)
                #pragma unroll
                for (int jn = 0; jn < 2; jn++)
                    mma16816(acc[im][jn], a[im], b[jn]);
        }
        if (c + 1 < nch) {
            bf16* Sd = sm + ((c + 1) & 1) * STG;
            #pragma unroll
            for (int i = 0; i < IM; i++) *(uint4*)&Sd[(lr + 16 * i) * SMS + lc] = pa[i];
            bf16* Bd = Sd + MT * SMS;
            #pragma unroll
            for (int i = 0; i < 8; i++) *(uint4*)&Bd[(lr + 16 * i) * SMS + lc] = pb[i];
            if (c + 2 < nch) {
                int off = (c + 2) * 128;
                #pragma unroll
                for (int i = 0; i < IM; i++) pa[i] = *(const uint4*)(Abase + i * rs + off);
                #pragma unroll
                for (int i = 0; i < 8; i++) pb[i] = *(const uint4*)(Bbase + i * rs + off);
            }
            __syncthreads();
        }
    }

    // ---------------- epilogues ----------------
    if constexpr (MODE == 0) {
        float* Cz = C + (size_t)blockIdx.z * 1024 * N;
        #pragma unroll
        for (int im = 0; im < IM; im++)
            #pragma unroll
            for (int jn = 0; jn < 2; jn++) {
                int r0 = mblk * MT + im * 16 + g;
                int cb = nblk * 128 + wn * 16 + jn * 8 + 2 * t;
                *(float2*)&Cz[(size_t)r0 * N + cb] = make_float2(acc[im][jn][0], acc[im][jn][1]);
                *(float2*)&Cz[(size_t)(r0 + 8) * N + cb] = make_float2(acc[im][jn][2], acc[im][jn][3]);
            }
    } else if constexpr (MODE == 1) {
        #pragma unroll
        for (int im = 0; im < IM; im++)
            #pragma unroll
            for (int jn = 0; jn < 2; jn++) {
                int cb = wn * 16 + jn * 8 + 2 * t;
                float bb0 = 200.0f * __ldg(&b0[cb]), bb1 = 200.0f * __ldg(&b0[cb + 1]);
                #pragma unroll
                for (int pr = 0; pr < 2; pr++) {
                    int row = mblk * MT + im * 16 + g + pr * 8;
                    float v0 = tanhf((acc[im][jn][2 * pr] + bb0) * (1.0f / 1024.0f));
                    float v1 = tanhf((acc[im][jn][2 * pr + 1] + bb1) * (1.0f / 1024.0f));
                    *(float2*)&g_sup[row * Dm + cb] = make_float2(v0, v1);
                    uint32_t hp, lp; splitp(v0, v1, hp, lp);
                    bf16* sa = g_supA + (size_t)row * 384;
                    *(uint32_t*)&sa[cb] = hp;
                    *(uint32_t*)&sa[128 + cb] = hp;
                    *(uint32_t*)&sa[256 + cb] = lp;
                }
            }
    } else if constexpr (MODE == 2) {
        #pragma unroll
        for (int im = 0; im < IM; im++)
            #pragma unroll
            for (int jn = 0; jn < 2; jn++) {
                int cb = nblk * 128 + wn * 16 + jn * 8 + 2 * t;
                float bb0 = __ldg(&b0[cb]), bb1 = __ldg(&b0[cb + 1]);
                #pragma unroll
                for (int pr = 0; pr < 2; pr++) {
                    int row = mblk * MT + im * 16 + g + pr * 8;
                    float v0 = fmaxf(acc[im][jn][2 * pr] + bb0, 0.0f);
                    float v1 = fmaxf(acc[im][jn][2 * pr + 1] + bb1, 0.0f);
                    uint32_t hp, lp; splitp(v0, v1, hp, lp);
                    bf16* ha = g_hidA + (size_t)row * 768;
                    *(uint32_t*)&ha[cb] = hp;
                    *(uint32_t*)&ha[256 + cb] = hp;
                    *(uint32_t*)&ha[512 + cb] = lp;
                }
            }
    } else if constexpr (MODE == 3) {   // MT == 32 only
        for (int i = tid; i < 32; i += 256) { rsum[i] = 0.f; rsq[i] = 0.f; rn2[i] = 0.f; }
        __syncthreads();
        #pragma unroll
        for (int im = 0; im < IM; im++) {
            float s0 = 0.f, s1 = 0.f, q0 = 0.f, q1 = 0.f;
            int ra = im * 16 + g;
            #pragma unroll
            for (int jn = 0; jn < 2; jn++) {
                int cb = wn * 16 + jn * 8 + 2 * t;
                float bb0 = __ldg(&b0[cb]), bb1 = __ldg(&b0[cb + 1]);
                int rowg0 = mblk * MT + ra;
                float2 s0v = *(const float2*)&g_sup[rowg0 * Dm + cb];
                float2 s1v = *(const float2*)&g_sup[(rowg0 + 8) * Dm + cb];
                float z0 = acc[im][jn][0] + bb0 + s0v.x;
                float z1 = acc[im][jn][1] + bb1 + s0v.y;
                float z2 = acc[im][jn][2] + bb0 + s1v.x;
                float z3 = acc[im][jn][3] + bb1 + s1v.y;
                acc[im][jn][0] = z0; acc[im][jn][1] = z1;
                acc[im][jn][2] = z2; acc[im][jn][3] = z3;
                s0 += z0 + z1; q0 += z0 * z0 + z1 * z1;
                s1 += z2 + z3; q1 += z2 * z2 + z3 * z3;
            }
            atomicAdd(&rsum[ra], s0); atomicAdd(&rsq[ra], q0);
            atomicAdd(&rsum[ra + 8], s1); atomicAdd(&rsq[ra + 8], q1);
        }
        __syncthreads();
        #pragma unroll
        for (int im = 0; im < IM; im++) {
            int ra = im * 16 + g;
            float mu0 = rsum[ra] * (1.0f / 128.0f);
            float mu1 = rsum[ra + 8] * (1.0f / 128.0f);
            float sd0 = sqrtf(fmaxf((rsq[ra] - 128.0f * mu0 * mu0) * (1.0f / 127.0f), 0.f)) + 1e-3f;
            float sd1 = sqrtf(fmaxf((rsq[ra + 8] - 128.0f * mu1 * mu1) * (1.0f / 127.0f), 0.f)) + 1e-3f;
            float i0 = 1.0f / sd0, i1 = 1.0f / sd1;
            float n20 = 0.f, n21 = 0.f;
            #pragma unroll
            for (int jn = 0; jn < 2; jn++) {
                int cb = wn * 16 + jn * 8 + 2 * t;
                float la0 = __ldg(&b1[cb]), la1 = __ldg(&b1[cb + 1]);
                float lb0 = __ldg(&b2[cb]), lb1 = __ldg(&b2[cb + 1]);
                float sg0 = (acc[im][jn][0] - mu0) * i0 * la0 + lb0;
                float sg1 = (acc[im][jn][1] - mu0) * i0 * la1 + lb1;
                float sg2 = (acc[im][jn][2] - mu1) * i1 * la0 + lb0;
                float sg3 = (acc[im][jn][3] - mu1) * i1 * la1 + lb1;
                acc[im][jn][0] = sg0; acc[im][jn][1] = sg1;
                acc[im][jn][2] = sg2; acc[im][jn][3] = sg3;
                n20 += sg0 * sg0 + sg1 * sg1;
                n21 += sg2 * sg2 + sg3 * sg3;
            }
            atomicAdd(&rn2[ra], n20); atomicAdd(&rn2[ra + 8], n21);
        }
        __syncthreads();
        #pragma unroll
        for (int im = 0; im < IM; im++) {
            int ra = im * 16 + g;
            #pragma unroll
            for (int jn = 0; jn < 2; jn++) {
                int cb = wn * 16 + jn * 8 + 2 * t;
                #pragma unroll
                for (int pr = 0; pr < 2; pr++) {
                    int row = mblk * MT + ra + pr * 8;
                    float v0 = acc[im][jn][2 * pr], v1 = acc[im][jn][2 * pr + 1];
                    *(float2*)&g_sg[row * Dm + cb] = make_float2(v0, v1);
                    uint32_t hp, lp; splitp(v0, v1, hp, lp);
                    bf16* sb = g_sgB + (size_t)row * 384;
                    *(uint32_t*)&sb[cb] = hp;
                    *(uint32_t*)&sb[128 + cb] = lp;
                    *(uint32_t*)&sb[256 + cb] = hp;
                    bf16 h0, l0, h1, l1;
                    split2(v0, h0, l0); split2(v1, h1, l1);
                    size_t tb0 = (size_t)cb * 3072 + (row >> 7) * 384 + (row & 127);
                    size_t tb1 = tb0 + 3072;
                    g_sgT[tb0] = h0; g_sgT[tb0 + 128] = l0; g_sgT[tb0 + 256] = h0;
                    g_sgT[tb1] = h1; g_sgT[tb1 + 128] = l1; g_sgT[tb1 + 256] = h1;
                }
            }
            if (wn == 0 && t == 0) {
                g_sgn2[mblk * MT + ra] = rn2[ra];
                g_sgn2[mblk * MT + ra + 8] = rn2[ra + 8];
            }
        }
    } else {
        constexpr int first = (MODE == 4);
        #pragma unroll
        for (int im = 0; im < IM; im++)
            #pragma unroll
            for (int jn = 0; jn < 2; jn++) {
                int r0 = mblk * MT + im * 16 + g;
                int base8 = nblk * 128 + wn * 16 + jn * 8;
                int cb = base8 + 2 * t;
                float v0 = acc[im][jn][0], v1 = acc[im][jn][1];
                float v2 = acc[im][jn][2], v3 = acc[im][jn][3];
                if constexpr (first) {
                    float bb0 = __ldg(&g_bperm[cb]), bb1 = __ldg(&g_bperm[cb + 1]);
                    v0 += bb0; v1 += bb1; v2 += bb0; v3 += bb1;
                    *(float2*)&g_qWb[(size_t)r0 * G8 + cb] = make_float2(v0, v1);
                    *(float2*)&g_qWb[(size_t)(r0 + 8) * G8 + cb] = make_float2(v2, v3);
                } else {
                    float2 a0 = *(const float2*)&g_qWb[(size_t)r0 * G8 + cb];
                    float2 a1 = *(const float2*)&g_qWb[(size_t)(r0 + 8) * G8 + cb];
                    v0 += a0.x; v1 += a0.y; v2 += a1.x; v3 += a1.y;
                }
                float ex0 = __shfl_xor_sync(0xffffffffu, v0, 1);
                float ex1 = __shfl_xor_sync(0xffffffffu, v1, 1);
                float ex2 = __shfl_xor_sync(0xffffffffu, v2, 1);
                float ex3 = __shfl_xor_sync(0xffffffffu, v3, 1);
                float gi, gf, gg, go; int row;
                if ((t & 1) == 0) { gi = v0; gf = v1; gg = ex0; go = ex1; row = r0; }
                else             { gi = ex2; gf = ex3; gg = v2; go = v3; row = r0 + 8; }
                int j = (base8 >> 2) + (t >> 1);
                float cp = first ? 0.0f : g_c[row * D2 + j];
                float si = 1.0f / (1.0f + __expf(-gi));
                float sf = 1.0f / (1.0f + __expf(-gf));
                float so = 1.0f / (1.0f + __expf(-go));
                float cc = sf * cp + si * tanhf(gg);
                g_c[row * D2 + j] = cc;
                float h = so * tanhf(cc);
                if (j < Dm) {
                    float ho = g_qe[row * Dm + j] + h;
                    g_hout[row * Dm + j] = ho;
                    bf16 hh2, ll2; split2(ho, hh2, ll2);
                    bf16* ha = g_houtA + (size_t)row * 384;
                    ha[j] = hh2; ha[128 + j] = hh2; ha[256 + j] = ll2;
                    bf16* ra2 = g_hrA + (size_t)row * 768;
                    ra2[j] = hh2; ra2[256 + j] = hh2; ra2[512 + j] = ll2;
                }
            }
    }
}

// ================= softmax / reduce / cosine =================
__global__ void softmax_kernel() {
    __shared__ float s[8];
    int b = blockIdx.x, t = threadIdx.x;
    const float4* row = (const float4*)(g_scores + (size_t)b * Bsz);
    float4 x = row[t];
    float m = fmaxf(fmaxf(x.x, x.y), fmaxf(x.z, x.w));
    #pragma unroll
    for (int o = 16; o; o >>= 1) m = fmaxf(m, __shfl_xor_sync(0xffffffffu, m, o));
    if ((t & 31) == 0) s[t >> 5] = m;
    __syncthreads();
    m = fmaxf(fmaxf(fmaxf(s[0], s[1]), fmaxf(s[2], s[3])),
              fmaxf(fmaxf(s[4], s[5]), fmaxf(s[6], s[7])));
    __syncthreads();
    float e0 = __expf(x.x - m), e1 = __expf(x.y - m);
    float e2 = __expf(x.z - m), e3 = __expf(x.w - m);
    float l = e0 + e1 + e2 + e3;
    #pragma unroll
    for (int o = 16; o; o >>= 1) l += __shfl_xor_sync(0xffffffffu, l, o);
    if ((t & 31) == 0) s[t >> 5] = l;
    __syncthreads();
    l = s[0] + s[1] + s[2] + s[3] + s[4] + s[5] + s[6] + s[7];
    float inv = 1.0f / l;
    float p0 = e0 * inv, p1 = e1 * inv, p2 = e2 * inv, p3 = e3 * inv;
    int j0 = t * 4;
    int ks = j0 >> 7, jl0 = j0 & 127;
    bf16* base = g_P + (size_t)b * 3072 + ks * 384 + jl0;
    uint32_t hp0, lp0, hp1, lp1;
    splitp(p0, p1, hp0, lp0);
    splitp(p2, p3, hp1, lp1);
    ((uint32_t*)base)[0] = hp0; ((uint32_t*)base)[1] = hp1;
    ((uint32_t*)(base + 128))[0] = hp0; ((uint32_t*)(base + 128))[1] = hp1;
    ((uint32_t*)(base + 256))[0] = lp0; ((uint32_t*)(base + 256))[1] = lp1;
}

__global__ void reduce_r_kernel() {
    int b = blockIdx.x, d = threadIdx.x;
    float r = 0.f;
    #pragma unroll
    for (int z = 0; z < 8; z++) r += g_rp[(size_t)z * Bsz * Dm + b * Dm + d];
    bf16 h, l; split2(r, h, l);
    bf16* ra = g_hrA + (size_t)b * 768;
    ra[128 + d] = h; ra[384 + d] = h; ra[640 + d] = l;
}

__global__ void cosine_kernel(float* __restrict__ out) {
    __shared__ float s[4];
    int b = blockIdx.x, d = threadIdx.x;
    float ho = g_hout[b * Dm + d];
    float sg = g_sg[b * Dm + d];
    float cross = ho * sg, n1 = ho * ho;
    #pragma unroll
    for (int o = 16; o; o >>= 1) {
        cross += __shfl_xor_sync(0xffffffffu, cross, o);
        n1 += __shfl_xor_sync(0xffffffffu, n1, o);
    }
    if ((d & 31) == 0) { s[d >> 5] = cross; }
    __syncthreads();
    float cr = s[0] + s[1] + s[2] + s[3];
    __syncthreads();
    if ((d & 31) == 0) { s[d >> 5] = n1; }
    __syncthreads();
    float nn = s[0] + s[1] + s[2] + s[3];
    if (d == 0) out[b] = cr * rsqrtf(nn * g_sgn2[b]);
}

// ================= host orchestration =================
#define SM32 (2 * (160 * SMS) * 2)
#define SM64 (2 * (192 * SMS) * 2)
extern "C" void kernel_launch(void* const* d_in, const int* in_sizes, int n_in,
                              void* d_out, int out_size) {
    (void)in_sizes; (void)n_in; (void)out_size;
    const int*   relations = (const int*)d_in[0];
    const int*   entities  = (const int*)d_in[1];
    const int*   query     = (const int*)d_in[2];
    const float* emb       = (const float*)d_in[3];
    const float* gcn_w     = (const float*)d_in[4];
    const float* gcn_b     = (const float*)d_in[5];
    const float* p1_w      = (const float*)d_in[6];
    const float* p1_b      = (const float*)d_in[7];
    const float* p2_w      = (const float*)d_in[8];
    const float* p2_b      = (const float*)d_in[9];
    const float* ln_a      = (const float*)d_in[10];
    const float* ln_b      = (const float*)d_in[11];
    const float* w_ih      = (const float*)d_in[12];
    const float* w_hh      = (const float*)d_in[13];
    const float* b_ih      = (const float*)d_in[14];
    const float* b_hh      = (const float*)d_in[15];
    float* out = (float*)d_out;

    cudaFuncSetAttribute(gemm_tc<0, 64>, cudaFuncAttributeMaxDynamicSharedMemorySize, SM64);
    cudaFuncSetAttribute(gemm_tc<1, 32>, cudaFuncAttributeMaxDynamicSharedMemorySize, SM32);
    cudaFuncSetAttribute(gemm_tc<2, 32>, cudaFuncAttributeMaxDynamicSharedMemorySize, SM32);
    cudaFuncSetAttribute(gemm_tc<3, 32>, cudaFuncAttributeMaxDynamicSharedMemorySize, SM32);
    cudaFuncSetAttribute(gemm_tc<4, 64>, cudaFuncAttributeMaxDynamicSharedMemorySize, SM64);
    cudaFuncSetAttribute(gemm_tc<6, 64>, cudaFuncAttributeMaxDynamicSharedMemorySize, SM64);

    float *scores, *rp;
    bf16 *scatA, *qeA, *supA, *hidA, *houtA, *hrA, *P, *sgB, *sgT;
    bf16 *gcnB, *p1B, *p2B, *wihB, *whhB;
    cudaGetSymbolAddress((void**)&scores, g_scores);
    cudaGetSymbolAddress((void**)&rp, g_rp);
    cudaGetSymbolAddress((void**)&scatA, g_scatA);
    cudaGetSymbolAddress((void**)&qeA, g_qeA);
    cudaGetSymbolAddress((void**)&supA, g_supA);
    cudaGetSymbolAddress((void**)&hidA, g_hidA);
    cudaGetSymbolAddress((void**)&houtA, g_houtA);
    cudaGetSymbolAddress((void**)&hrA, g_hrA);
    cudaGetSymbolAddress((void**)&P, g_P);
    cudaGetSymbolAddress((void**)&sgB, g_sgB);
    cudaGetSymbolAddress((void**)&sgT, g_sgT);
    cudaGetSymbolAddress((void**)&gcnB, g_gcnB);
    cudaGetSymbolAddress((void**)&p1B, g_p1B);
    cudaGetSymbolAddress((void**)&p2B, g_p2B);
    cudaGetSymbolAddress((void**)&wihB, g_wihB);
    cudaGetSymbolAddress((void**)&whhB, g_whhB);

    // 1) fused weight conversions + bias permutation + gather-sum
    front_kernel<<<2561 + Bsz, 256>>>(gcn_w, p1_w, p2_w, w_ih, w_hh, b_ih, b_hh,
                                      relations, entities, query, emb);
    // 2) sup = tanh((scat.gcn^T + 200b)/1024)
    gemm_tc<1, 32><<<dim3(1, 32), 256, SM32>>>(scatA, gcnB, nullptr, Dm, 768, 768,
                                               gcn_b, nullptr, nullptr);
    // 3) hidA = relu(sup.p1^T + b)
    gemm_tc<2, 32><<<dim3(2, 32), 256, SM32>>>(supA, p1B, nullptr, D2, 384, 384,
                                               p1_b, nullptr, nullptr);
    // 4) z = hid.p2^T + b + sup; fused layernorm
    gemm_tc<3, 32><<<dim3(1, 32), 256, SM32>>>(hidA, p2B, nullptr, Dm, 768, 768,
                                               p2_b, ln_a, ln_b);
    // 5) qWb + first LSTM step (one-wave MT=64 grid)
    gemm_tc<4, 64><<<dim3(8, 16), 256, SM64>>>(qeA, wihB, nullptr, G8, 384, 384,
                                               nullptr, nullptr, nullptr);
    // 6) 3 attention+LSTM iterations
    for (int s = 1; s < 4; s++) {
        gemm_tc<0, 64><<<dim3(8, 16), 256, SM64>>>(houtA, sgB, scores, Bsz, 384, 384,
                                                   nullptr, nullptr, nullptr);
        softmax_kernel<<<Bsz, 256>>>();
        gemm_tc<0, 64><<<dim3(1, 16, 8), 256, SM64>>>(P, sgT, rp, Dm, 3072, 384,
                                                      nullptr, nullptr, nullptr);
        reduce_r_kernel<<<Bsz, Dm>>>();
        gemm_tc<6, 64><<<dim3(8, 16), 256, SM64>>>(hrA, whhB, nullptr, G8, 768, 768,
                                                   nullptr, nullptr, nullptr);
    }
    // 7) cosine
    cosine_kernel<<<Bsz, Dm>>>(out);
}

// round 16
// speedup vs baseline: 1.2697x; 1.0065x over previous
#include <cuda_runtime.h>
#include <cuda_bf16.h>
#include <math.h>
#include <cstdint>

#define Bsz 1024
#define Kn  200
#define Dm  128
#define D2  256
#define G8  1024

typedef __nv_bfloat16 bf16;

__device__ __forceinline__ void split2(float x, bf16& h, bf16& l) {
    h = __float2bfloat16(x);
    l = __float2bfloat16(x - __bfloat162float(h));
}
__device__ __forceinline__ uint32_t pk2(bf16 a, bf16 b) {
    uint16_t ua = *(uint16_t*)&a, ub = *(uint16_t*)&b;
    return (uint32_t)ua | ((uint32_t)ub << 16);
}
__device__ __forceinline__ void splitp(float x0, float x1, uint32_t& hp, uint32_t& lp) {
    bf16 h0, l0, h1, l1;
    split2(x0, h0, l0); split2(x1, h1, l1);
    hp = pk2(h0, h1); lp = pk2(l0, l1);
}

__device__ __forceinline__ void mma16816(float* c, const uint32_t* a, const uint32_t* b) {
    asm volatile(
        "mma.sync.aligned.m16n8k16.row.col.f32.bf16.bf16.f32 "
        "{%0,%1,%2,%3}, {%4,%5,%6,%7}, {%8,%9}, {%0,%1,%2,%3};"
        : "+f"(c[0]), "+f"(c[1]), "+f"(c[2]), "+f"(c[3])
        : "r"(a[0]), "r"(a[1]), "r"(a[2]), "r"(a[3]), "r"(b[0]), "r"(b[1]));
}

// ================= scratch =================
__device__ float g_qe[Bsz * Dm];
__device__ float g_sup[Bsz * Dm];
__device__ float g_sg[Bsz * Dm];
__device__ float g_sgn2[Bsz];
__device__ float g_qWb[Bsz * G8];
__device__ float g_scores[Bsz * Bsz];
__device__ float g_c[Bsz * D2];
__device__ float g_hout[Bsz * Dm];
__device__ float g_rp[8 * Bsz * Dm];
__device__ float g_bperm[G8];

__device__ bf16 g_scatA[Bsz * 768];
__device__ bf16 g_qeA[Bsz * 384];
__device__ bf16 g_supA[Bsz * 384];
__device__ bf16 g_hidA[Bsz * 768];
__device__ bf16 g_houtA[Bsz * 384];
__device__ bf16 g_hrA[Bsz * 768];
__device__ bf16 g_P[Bsz * 3072];
__device__ bf16 g_sgB[Bsz * 384];
__device__ bf16 g_sgT[Dm * 3072];
__device__ bf16 g_gcnB[Dm * 768];
__device__ bf16 g_p1B[D2 * 384];
__device__ bf16 g_p2B[Dm * 768];
__device__ bf16 g_wihB[G8 * 384];
__device__ bf16 g_whhB[G8 * 768];

// ================= fused front: weight conversion + gather-sum =================
__device__ __forceinline__ void convB_row(const float* src, bf16* dst, int srow,
                                          int drow, int K, int j) {
    if (j < K) {
        bf16 h, l; split2(src[(size_t)srow * K + j], h, l);
        bf16* d = dst + (size_t)drow * 3 * K;
        d[j] = h; d[K + j] = l; d[2 * K + j] = h;
    }
}
__global__ void front_kernel(const float* __restrict__ gcn_w, const float* __restrict__ p1_w,
                             const float* __restrict__ p2_w, const float* __restrict__ w_ih,
                             const float* __restrict__ w_hh, const float* __restrict__ b_ih,
                             const float* __restrict__ b_hh,
                             const int* __restrict__ rel, const int* __restrict__ ent,
                             const int* __restrict__ query, const float* __restrict__ emb) {
    int blk = blockIdx.x, j = threadIdx.x;
    if (blk < 128) {
        convB_row(gcn_w, g_gcnB, blk, blk, 256, j);
    } else if (blk < 384) {
        convB_row(p1_w, g_p1B, blk - 128, blk - 128, 128, j);
    } else if (blk < 512) {
        convB_row(p2_w, g_p2B, blk - 384, blk - 384, 256, j);
    } else if (blk < 1536) {
        int n = blk - 512;
        convB_row(w_ih, g_wihB, n, (n & 255) * 4 + (n >> 8), 128, j);
    } else if (blk < 2560) {
        int n = blk - 1536;
        convB_row(w_hh, g_whhB, n, (n & 255) * 4 + (n >> 8), 256, j);
    } else if (blk == 2560) {
        #pragma unroll
        for (int gidx = 0; gidx < 4; gidx++) {
            int n = gidx * 256 + j;
            g_bperm[j * 4 + gidx] = b_ih[n] + b_hh[n];
        }
    } else {
        __shared__ int sidx[2 * Kn];
        int b = blk - 2561;
        int half = j >> 7;          // 0 rel, 1 ent
        int d = j & 127;
        if (half == 0) {
            for (int i = d; i < Kn; i += 128) sidx[i] = rel[b * Kn + i];
        } else {
            for (int i = d; i < Kn; i += 128) sidx[Kn + i] = ent[b * Kn + i];
        }
        __syncthreads();
        const int* idx = sidx + half * Kn;
        float a = 0.f;
        #pragma unroll 8
        for (int k = 0; k < Kn; k++) a += __ldg(&emb[(size_t)idx[k] * Dm + d]);
        bf16 h, l;
        bf16* sa = g_scatA + (size_t)b * 768;
        split2(a, h, l);
        if (half == 0) { sa[d] = h; sa[256 + d] = h; sa[512 + d] = l; }
        else           { sa[128 + d] = h; sa[384 + d] = h; sa[640 + d] = l; }
        if (half == 0) {
            float qv = emb[(size_t)query[b] * Dm + d];
            g_qe[b * Dm + d] = qv;
            bf16* qa = g_qeA + (size_t)b * 384;
            split2(qv, h, l); qa[d] = h; qa[128 + d] = h; qa[256 + d] = l;
        }
    }
}

// ================= bf16 mma GEMM, CTA tile MTx128, BK=128, double-buffered =====
// 8 warps, warp tile MTx16. MODE: 0 store; 1 SUP; 2 HID; 3 Z+LN; 4 QWB+LSTM1; 6 HH+LSTM
#define SMS 136
template <int MODE, int MT>
__global__ __launch_bounds__(256, (MT <= 32) ? 2 : 1)
void gemm_tc(const bf16* __restrict__ A, const bf16* __restrict__ B,
             float* __restrict__ C, int N, int K3, int klen,
             const float* __restrict__ b0, const float* __restrict__ b1,
             const float* __restrict__ b2) {
    constexpr int IM = MT / 16;
    constexpr int STG = (MT + 128) * SMS;
    extern __shared__ bf16 sm[];
    __shared__ float rsum[32], rsq[32], rn2[32];
    int tid = threadIdx.x;
    int wid = tid >> 5, lane = tid & 31;
    int g = lane >> 2, t = lane & 3;
    int wn = wid;
    int nblk = blockIdx.x, mblk = blockIdx.y;
    int koff = blockIdx.z * klen;
    const bf16* Ab = A + (size_t)(mblk * MT) * K3 + koff;
    const bf16* Bb = B + (size_t)(nblk * 128) * K3 + koff;

    float acc[IM][2][4];
    #pragma unroll
    for (int i = 0; i < IM; i++)
        #pragma unroll
        for (int j = 0; j < 2; j++)
            #pragma unroll
            for (int q = 0; q < 4; q++) acc[i][j][q] = 0.f;

    int lr = tid >> 4;
    int lc = (tid & 15) * 8;
    int nch = klen >> 7;
    const bf16* Abase = Ab + (size_t)lr * K3 + lc;
    const bf16* Bbase = Bb + (size_t)lr * K3 + lc;
    size_t rs = (size_t)16 * K3;

    uint4 pa[IM], pb[8];
    #pragma unroll
    for (int i = 0; i < IM; i++) pa[i] = *(const uint4*)(Abase + i * rs);
    #pragma unroll
    for (int i = 0; i < 8; i++) pb[i] = *(const uint4*)(Bbase + i * rs);
    {
        bf16* Sd = sm;
        #pragma unroll
        for (int i = 0; i < IM; i++) *(uint4*)&Sd[(lr + 16 * i) * SMS + lc] = pa[i];
        bf16* Bd = sm + MT * SMS;
        #pragma unroll
        for (int i = 0; i < 8; i++) *(uint4*)&Bd[(lr + 16 * i) * SMS + lc] = pb[i];
    }
    if (nch > 1) {
        #pragma unroll
        for (int i = 0; i < IM; i++) pa[i] = *(const uint4*)(Abase + i * rs + 128);
        #pragma unroll
        for (int i = 0; i < 8; i++) pb[i] = *(const uint4*)(Bbase + i * rs + 128);
    }
    __syncthreads();

    for (int c = 0; c < nch; c++) {
        const bf16* As = sm + (c & 1) * STG;
        const bf16* Bs = As + MT * SMS;
        #pragma unroll
        for (int k = 0; k < 8; k++) {
            uint32_t a[IM][4], b[2][2];
            #pragma unroll
            for (int im = 0; im < IM; im++) {
                int r = im * 16 + g;
                a[im][0] = *(const uint32_t*)&As[r * SMS + k * 16 + 2 * t];
                a[im][1] = *(const uint32_t*)&As[(r + 8) * SMS + k * 16 + 2 * t];
                a[im][2] = *(const uint32_t*)&As[r * SMS + k * 16 + 2 * t + 8];
                a[im][3] = *(const uint32_t*)&As[(r + 8) * SMS + k * 16 + 2 * t + 8];
            }
            #pragma unroll
            for (int jn = 0; jn < 2; jn++) {
                int n = wn * 16 + jn * 8 + g;
                b[jn][0] = *(const uint32_t*)&Bs[n * SMS + k * 16 + 2 * t];
                b[jn][1] = *(const uint32_t*)&Bs[n * SMS + k * 16 + 2 * t + 8];
            }
            #pragma unroll
            for (int im = 0; im < IM; im++)
                #pragma unroll
                for (int jn = 0; jn < 2; jn++)
                    mma16816(acc[im][jn], a[im], b[jn]);
        }
        if (c + 1 < nch) {
            bf16* Sd = sm + ((c + 1) & 1) * STG;
            #pragma unroll
            for (int i = 0; i < IM; i++) *(uint4*)&Sd[(lr + 16 * i) * SMS + lc] = pa[i];
            bf16* Bd = Sd + MT * SMS;
            #pragma unroll
            for (int i = 0; i < 8; i++) *(uint4*)&Bd[(lr + 16 * i) * SMS + lc] = pb[i];
            if (c + 2 < nch) {
                int off = (c + 2) * 128;
                #pragma unroll
                for (int i = 0; i < IM; i++) pa[i] = *(const uint4*)(Abase + i * rs + off);
                #pragma unroll
                for (int i = 0; i < 8; i++) pb[i] = *(const uint4*)(Bbase + i * rs + off);
            }
            __syncthreads();
        }
    }

    // ---------------- epilogues ----------------
    if constexpr (MODE == 0) {
        float* Cz = C + (size_t)blockIdx.z * 1024 * N;
        #pragma unroll
        for (int im = 0; im < IM; im++)
            #pragma unroll
            for (int jn = 0; jn < 2; jn++) {
                int r0 = mblk * MT + im * 16 + g;
                int cb = nblk * 128 + wn * 16 + jn * 8 + 2 * t;
                *(float2*)&Cz[(size_t)r0 * N + cb] = make_float2(acc[im][jn][0], acc[im][jn][1]);
                *(float2*)&Cz[(size_t)(r0 + 8) * N + cb] = make_float2(acc[im][jn][2], acc[im][jn][3]);
            }
    } else if constexpr (MODE == 1) {
        #pragma unroll
        for (int im = 0; im < IM; im++)
            #pragma unroll
            for (int jn = 0; jn < 2; jn++) {
                int cb = wn * 16 + jn * 8 + 2 * t;
                float bb0 = 200.0f * __ldg(&b0[cb]), bb1 = 200.0f * __ldg(&b0[cb + 1]);
                #pragma unroll
                for (int pr = 0; pr < 2; pr++) {
                    int row = mblk * MT + im * 16 + g + pr * 8;
                    float v0 = tanhf((acc[im][jn][2 * pr] + bb0) * (1.0f / 1024.0f));
                    float v1 = tanhf((acc[im][jn][2 * pr + 1] + bb1) * (1.0f / 1024.0f));
                    *(float2*)&g_sup[row * Dm + cb] = make_float2(v0, v1);
                    uint32_t hp, lp; splitp(v0, v1, hp, lp);
                    bf16* sa = g_supA + (size_t)row * 384;
                    *(uint32_t*)&sa[cb] = hp;
                    *(uint32_t*)&sa[128 + cb] = hp;
                    *(uint32_t*)&sa[256 + cb] = lp;
                }
            }
    } else if constexpr (MODE == 2) {
        #pragma unroll
        for (int im = 0; im < IM; im++)
            #pragma unroll
            for (int jn = 0; jn < 2; jn++) {
                int cb = nblk * 128 + wn * 16 + jn * 8 + 2 * t;
                float bb0 = __ldg(&b0[cb]), bb1 = __ldg(&b0[cb + 1]);
                #pragma unroll
                for (int pr = 0; pr < 2; pr++) {
                    int row = mblk * MT + im * 16 + g + pr * 8;
                    float v0 = fmaxf(acc[im][jn][2 * pr] + bb0, 0.0f);
                    float v1 = fmaxf(acc[im][jn][2 * pr + 1] + bb1, 0.0f);
                    uint32_t hp, lp; splitp(v0, v1, hp, lp);
                    bf16* ha = g_hidA + (size_t)row * 768;
                    *(uint32_t*)&ha[cb] = hp;
                    *(uint32_t*)&ha[256 + cb] = hp;
                    *(uint32_t*)&ha[512 + cb] = lp;
                }
            }
    } else if constexpr (MODE == 3) {   // MT <= 32 only
        for (int i = tid; i < 32; i += 256) { rsum[i] = 0.f; rsq[i] = 0.f; rn2[i] = 0.f; }
        __syncthreads();
        #pragma unroll
        for (int im = 0; im < IM; im++) {
            float s0 = 0.f, s1 = 0.f, q0 = 0.f, q1 = 0.f;
            int ra = im * 16 + g;
            #pragma unroll
            for (int jn = 0; jn < 2; jn++) {
                int cb = wn * 16 + jn * 8 + 2 * t;
                float bb0 = __ldg(&b0[cb]), bb1 = __ldg(&b0[cb + 1]);
                int rowg0 = mblk * MT + ra;
                float2 s0v = *(const float2*)&g_sup[rowg0 * Dm + cb];
                float2 s1v = *(const float2*)&g_sup[(rowg0 + 8) * Dm + cb];
                float z0 = acc[im][jn][0] + bb0 + s0v.x;
                float z1 = acc[im][jn][1] + bb1 + s0v.y;
                float z2 = acc[im][jn][2] + bb0 + s1v.x;
                float z3 = acc[im][jn][3] + bb1 + s1v.y;
                acc[im][jn][0] = z0; acc[im][jn][1] = z1;
                acc[im][jn][2] = z2; acc[im][jn][3] = z3;
                s0 += z0 + z1; q0 += z0 * z0 + z1 * z1;
                s1 += z2 + z3; q1 += z2 * z2 + z3 * z3;
            }
            atomicAdd(&rsum[ra], s0); atomicAdd(&rsq[ra], q0);
            atomicAdd(&rsum[ra + 8], s1); atomicAdd(&rsq[ra + 8], q1);
        }
        __syncthreads();
        #pragma unroll
        for (int im = 0; im < IM; im++) {
            int ra = im * 16 + g;
            float mu0 = rsum[ra] * (1.0f / 128.0f);
            float mu1 = rsum[ra + 8] * (1.0f / 128.0f);
            float sd0 = sqrtf(fmaxf((rsq[ra] - 128.0f * mu0 * mu0) * (1.0f / 127.0f), 0.f)) + 1e-3f;
            float sd1 = sqrtf(fmaxf((rsq[ra + 8] - 128.0f * mu1 * mu1) * (1.0f / 127.0f), 0.f)) + 1e-3f;
            float i0 = 1.0f / sd0, i1 = 1.0f / sd1;
            float n20 = 0.f, n21 = 0.f;
            #pragma unroll
            for (int jn = 0; jn < 2; jn++) {
                int cb = wn * 16 + jn * 8 + 2 * t;
                float la0 = __ldg(&b1[cb]), la1 = __ldg(&b1[cb + 1]);
                float lb0 = __ldg(&b2[cb]), lb1 = __ldg(&b2[cb + 1]);
                float sg0 = (acc[im][jn][0] - mu0) * i0 * la0 + lb0;
                float sg1 = (acc[im][jn][1] - mu0) * i0 * la1 + lb1;
                float sg2 = (acc[im][jn][2] - mu1) * i1 * la0 + lb0;
                float sg3 = (acc[im][jn][3] - mu1) * i1 * la1 + lb1;
                acc[im][jn][0] = sg0; acc[im][jn][1] = sg1;
                acc[im][jn][2] = sg2; acc[im][jn][3] = sg3;
                n20 += sg0 * sg0 + sg1 * sg1;
                n21 += sg2 * sg2 + sg3 * sg3;
            }
            atomicAdd(&rn2[ra], n20); atomicAdd(&rn2[ra + 8], n21);
        }
        __syncthreads();
        #pragma unroll
        for (int im = 0; im < IM; im++) {
            int ra = im * 16 + g;
            #pragma unroll
            for (int jn = 0; jn < 2; jn++) {
                int cb = wn * 16 + jn * 8 + 2 * t;
                #pragma unroll
                for (int pr = 0; pr < 2; pr++) {
                    int row = mblk * MT + ra + pr * 8;
                    float v0 = acc[im][jn][2 * pr], v1 = acc[im][jn][2 * pr + 1];
                    *(float2*)&g_sg[row * Dm + cb] = make_float2(v0, v1);
                    uint32_t hp, lp; splitp(v0, v1, hp, lp);
                    bf16* sb = g_sgB + (size_t)row * 384;
                    *(uint32_t*)&sb[cb] = hp;
                    *(uint32_t*)&sb[128 + cb] = lp;
                    *(uint32_t*)&sb[256 + cb] = hp;
                }
            }
            if (wn == 0 && t == 0) {
                g_sgn2[mblk * MT + ra] = rn2[ra];
                g_sgn2[mblk * MT + ra + 8] = rn2[ra + 8];
            }
        }
    } else {
        constexpr int first = (MODE == 4);
        #pragma unroll
        for (int im = 0; im < IM; im++)
            #pragma unroll
            for (int jn = 0; jn < 2; jn++) {
                int r0 = mblk * MT + im * 16 + g;
                int base8 = nblk * 128 + wn * 16 + jn * 8;
                int cb = base8 + 2 * t;
                float v0 = acc[im][jn][0], v1 = acc[im][jn][1];
                float v2 = acc[im][jn][2], v3 = acc[im][jn][3];
                if constexpr (first) {
                    float bb0 = __ldg(&g_bperm[cb]), bb1 = __ldg(&g_bperm[cb + 1]);
                    v0 += bb0; v1 += bb1; v2 += bb0; v3 += bb1;
                    *(float2*)&g_qWb[(size_t)r0 * G8 + cb] = make_float2(v0, v1);
                    *(float2*)&g_qWb[(size_t)(r0 + 8) * G8 + cb] = make_float2(v2, v3);
                } else {
                    float2 a0 = *(const float2*)&g_qWb[(size_t)r0 * G8 + cb];
                    float2 a1 = *(const float2*)&g_qWb[(size_t)(r0 + 8) * G8 + cb];
                    v0 += a0.x; v1 += a0.y; v2 += a1.x; v3 += a1.y;
                }
                float ex0 = __shfl_xor_sync(0xffffffffu, v0, 1);
                float ex1 = __shfl_xor_sync(0xffffffffu, v1, 1);
                float ex2 = __shfl_xor_sync(0xffffffffu, v2, 1);
                float ex3 = __shfl_xor_sync(0xffffffffu, v3, 1);
                float gi, gf, gg, go; int row;
                if ((t & 1) == 0) { gi = v0; gf = v1; gg = ex0; go = ex1; row = r0; }
                else             { gi = ex2; gf = ex3; gg = v2; go = v3; row = r0 + 8; }
                int j = (base8 >> 2) + (t >> 1);
                float cp = first ? 0.0f : g_c[row * D2 + j];
                float si = 1.0f / (1.0f + __expf(-gi));
                float sf = 1.0f / (1.0f + __expf(-gf));
                float so = 1.0f / (1.0f + __expf(-go));
                float cc = sf * cp + si * tanhf(gg);
                g_c[row * D2 + j] = cc;
                float h = so * tanhf(cc);
                if (j < Dm) {
                    float ho = g_qe[row * Dm + j] + h;
                    g_hout[row * Dm + j] = ho;
                    bf16 hh2, ll2; split2(ho, hh2, ll2);
                    bf16* ha = g_houtA + (size_t)row * 384;
                    ha[j] = hh2; ha[128 + j] = hh2; ha[256 + j] = ll2;
                    bf16* ra2 = g_hrA + (size_t)row * 768;
                    ra2[j] = hh2; ra2[256 + j] = hh2; ra2[512 + j] = ll2;
                }
            }
    }
}

// ================= sgT transpose: g_sg (b-major) -> g_sgT (d-major, packed) ====
// 8 CTAs (one per 128-row b-group), 256 threads, smem tile stride 129 fp32.
#define SGT_SMEM (128 * 129 * 4)
__global__ __launch_bounds__(256, 1) void sgt_kernel() {
    extern __shared__ float sf[];
    int tid = threadIdx.x;
    int grp = blockIdx.x;
    #pragma unroll
    for (int i = 0; i < 16; i++) {
        int li = tid + i * 256;          // float4 index 0..4095
        int row = li >> 5;
        int c4 = (li & 31) * 4;
        float4 v = *(const float4*)&g_sg[(size_t)(grp * 128 + row) * Dm + c4];
        float* dst = &sf[row * 129 + c4];
        dst[0] = v.x; dst[1] = v.y; dst[2] = v.z; dst[3] = v.w;
    }
    __syncthreads();
    int d = tid >> 1, half = tid & 1;
    bf16* base = g_sgT + (size_t)d * 3072 + grp * 384;
    for (int bb = 0; bb < 8; bb++) {
        int b0 = half * 64 + bb * 8;
        uint32_t hp[4], lp[4];
        #pragma unroll
        for (int q = 0; q < 4; q++) {
            float x0 = sf[(b0 + 2 * q) * 129 + d];
            float x1 = sf[(b0 + 2 * q + 1) * 129 + d];
            splitp(x0, x1, hp[q], lp[q]);
        }
        uint4 h4 = make_uint4(hp[0], hp[1], hp[2], hp[3]);
        uint4 l4 = make_uint4(lp[0], lp[1], lp[2], lp[3]);
        *(uint4*)&base[b0] = h4;
        *(uint4*)&base[128 + b0] = l4;
        *(uint4*)&base[256 + b0] = h4;
    }
}

// ================= softmax / reduce / cosine =================
__global__ void softmax_kernel() {
    __shared__ float s[8];
    int b = blockIdx.x, t = threadIdx.x;
    const float4* row = (const float4*)(g_scores + (size_t)b * Bsz);
    float4 x = row[t];
    float m = fmaxf(fmaxf(x.x, x.y), fmaxf(x.z, x.w));
    #pragma unroll
    for (int o = 16; o; o >>= 1) m = fmaxf(m, __shfl_xor_sync(0xffffffffu, m, o));
    if ((t & 31) == 0) s[t >> 5] = m;
    __syncthreads();
    m = fmaxf(fmaxf(fmaxf(s[0], s[1]), fmaxf(s[2], s[3])),
              fmaxf(fmaxf(s[4], s[5]), fmaxf(s[6], s[7])));
    __syncthreads();
    float e0 = __expf(x.x - m), e1 = __expf(x.y - m);
    float e2 = __expf(x.z - m), e3 = __expf(x.w - m);
    float l = e0 + e1 + e2 + e3;
    #pragma unroll
    for (int o = 16; o; o >>= 1) l += __shfl_xor_sync(0xffffffffu, l, o);
    if ((t & 31) == 0) s[t >> 5] = l;
    __syncthreads();
    l = s[0] + s[1] + s[2] + s[3] + s[4] + s[5] + s[6] + s[7];
    float inv = 1.0f / l;
    float p0 = e0 * inv, p1 = e1 * inv, p2 = e2 * inv, p3 = e3 * inv;
    int j0 = t * 4;
    int ks = j0 >> 7, jl0 = j0 & 127;
    bf16* base = g_P + (size_t)b * 3072 + ks * 384 + jl0;
    uint32_t hp0, lp0, hp1, lp1;
    splitp(p0, p1, hp0, lp0);
    splitp(p2, p3, hp1, lp1);
    ((uint32_t*)base)[0] = hp0; ((uint32_t*)base)[1] = hp1;
    ((uint32_t*)(base + 128))[0] = hp0; ((uint32_t*)(base + 128))[1] = hp1;
    ((uint32_t*)(base + 256))[0] = lp0; ((uint32_t*)(base + 256))[1] = lp1;
}

__global__ void reduce_r_kernel() {
    int b = blockIdx.x, d = threadIdx.x;
    float r = 0.f;
    #pragma unroll
    for (int z = 0; z < 8; z++) r += g_rp[(size_t)z * Bsz * Dm + b * Dm + d];
    bf16 h, l; split2(r, h, l);
    bf16* ra = g_hrA + (size_t)b * 768;
    ra[128 + d] = h; ra[384 + d] = h; ra[640 + d] = l;
}

__global__ void cosine_kernel(float* __restrict__ out) {
    __shared__ float s[4];
    int b = blockIdx.x, d = threadIdx.x;
    float ho = g_hout[b * Dm + d];
    float sg = g_sg[b * Dm + d];
    float cross = ho * sg, n1 = ho * ho;
    #pragma unroll
    for (int o = 16; o; o >>= 1) {
        cross += __shfl_xor_sync(0xffffffffu, cross, o);
        n1 += __shfl_xor_sync(0xffffffffu, n1, o);
    }
    if ((d & 31) == 0) { s[d >> 5] = cross; }
    __syncthreads();
    float cr = s[0] + s[1] + s[2] + s[3];
    __syncthreads();
    if ((d & 31) == 0) { s[d >> 5] = n1; }
    __syncthreads();
    float nn = s[0] + s[1] + s[2] + s[3];
    if (d == 0) out[b] = cr * rsqrtf(nn * g_sgn2[b]);
}

// ================= host orchestration =================
#define SM16 (2 * (144 * SMS) * 2)
#define SM64 (2 * (192 * SMS) * 2)
extern "C" void kernel_launch(void* const* d_in, const int* in_sizes, int n_in,
                              void* d_out, int out_size) {
    (void)in_sizes; (void)n_in; (void)out_size;
    const int*   relations = (const int*)d_in[0];
    const int*   entities  = (const int*)d_in[1];
    const int*   query     = (const int*)d_in[2];
    const float* emb       = (const float*)d_in[3];
    const float* gcn_w     = (const float*)d_in[4];
    const float* gcn_b     = (const float*)d_in[5];
    const float* p1_w      = (const float*)d_in[6];
    const float* p1_b      = (const float*)d_in[7];
    const float* p2_w      = (const float*)d_in[8];
    const float* p2_b      = (const float*)d_in[9];
    const float* ln_a      = (const float*)d_in[10];
    const float* ln_b      = (const float*)d_in[11];
    const float* w_ih      = (const float*)d_in[12];
    const float* w_hh      = (const float*)d_in[13];
    const float* b_ih      = (const float*)d_in[14];
    const float* b_hh      = (const float*)d_in[15];
    float* out = (float*)d_out;

    cudaFuncSetAttribute(gemm_tc<0, 64>, cudaFuncAttributeMaxDynamicSharedMemorySize, SM64);
    cudaFuncSetAttribute(gemm_tc<1, 16>, cudaFuncAttributeMaxDynamicSharedMemorySize, SM16);
    cudaFuncSetAttribute(gemm_tc<2, 16>, cudaFuncAttributeMaxDynamicSharedMemorySize, SM16);
    cudaFuncSetAttribute(gemm_tc<3, 16>, cudaFuncAttributeMaxDynamicSharedMemorySize, SM16);
    cudaFuncSetAttribute(gemm_tc<4, 64>, cudaFuncAttributeMaxDynamicSharedMemorySize, SM64);
    cudaFuncSetAttribute(gemm_tc<6, 64>, cudaFuncAttributeMaxDynamicSharedMemorySize, SM64);
    cudaFuncSetAttribute(sgt_kernel, cudaFuncAttributeMaxDynamicSharedMemorySize, SGT_SMEM);

    float *scores, *rp;
    bf16 *scatA, *qeA, *supA, *hidA, *houtA, *hrA, *P, *sgB, *sgT;
    bf16 *gcnB, *p1B, *p2B, *wihB, *whhB;
    cudaGetSymbolAddress((void**)&scores, g_scores);
    cudaGetSymbolAddress((void**)&rp, g_rp);
    cudaGetSymbolAddress((void**)&scatA, g_scatA);
    cudaGetSymbolAddress((void**)&qeA, g_qeA);
    cudaGetSymbolAddress((void**)&supA, g_supA);
    cudaGetSymbolAddress((void**)&hidA, g_hidA);
    cudaGetSymbolAddress((void**)&houtA, g_houtA);
    cudaGetSymbolAddress((void**)&hrA, g_hrA);
    cudaGetSymbolAddress((void**)&P, g_P);
    cudaGetSymbolAddress((void**)&sgB, g_sgB);
    cudaGetSymbolAddress((void**)&sgT, g_sgT);
    cudaGetSymbolAddress((void**)&gcnB, g_gcnB);
    cudaGetSymbolAddress((void**)&p1B, g_p1B);
    cudaGetSymbolAddress((void**)&p2B, g_p2B);
    cudaGetSymbolAddress((void**)&wihB, g_wihB);
    cudaGetSymbolAddress((void**)&whhB, g_whhB);

    // 1) fused weight conversions + bias permutation + gather-sum
    front_kernel<<<2561 + Bsz, 256>>>(gcn_w, p1_w, p2_w, w_ih, w_hh, b_ih, b_hh,
                                      relations, entities, query, emb);
    // 2) sup = tanh((scat.gcn^T + 200b)/1024)
    gemm_tc<1, 16><<<dim3(1, 64), 256, SM16>>>(scatA, gcnB, nullptr, Dm, 768, 768,
                                               gcn_b, nullptr, nullptr);
    // 3) hidA = relu(sup.p1^T + b)
    gemm_tc<2, 16><<<dim3(2, 64), 256, SM16>>>(supA, p1B, nullptr, D2, 384, 384,
                                               p1_b, nullptr, nullptr);
    // 4) z = hid.p2^T + b + sup; fused layernorm
    gemm_tc<3, 16><<<dim3(1, 64), 256, SM16>>>(hidA, p2B, nullptr, Dm, 768, 768,
                                               p2_b, ln_a, ln_b);
    // 5) sgT transpose (coalesced)
    sgt_kernel<<<8, 256, SGT_SMEM>>>();
    // 6) qWb + first LSTM step
    gemm_tc<4, 64><<<dim3(8, 16), 256, SM64>>>(qeA, wihB, nullptr, G8, 384, 384,
                                               nullptr, nullptr, nullptr);
    // 7) 3 attention+LSTM iterations
    for (int s = 1; s < 4; s++) {
        gemm_tc<0, 64><<<dim3(8, 16), 256, SM64>>>(houtA, sgB, scores, Bsz, 384, 384,
                                                   nullptr, nullptr, nullptr);
        softmax_kernel<<<Bsz, 256>>>();
        gemm_tc<0, 64><<<dim3(1, 16, 8), 256, SM64>>>(P, sgT, rp, Dm, 3072, 384,
                                                      nullptr, nullptr, nullptr);
        reduce_r_kernel<<<Bsz, Dm>>>();
        gemm_tc<6, 64><<<dim3(8, 16), 256, SM64>>>(hrA, whhB, nullptr, G8, 768, 768,
                                                   nullptr, nullptr, nullptr);
    }
    // 8) cosine
    cosine_kernel<<<Bsz, Dm>>>(out);
}

// round 17
// speedup vs baseline: 1.2815x; 1.0093x over previous
#include <cuda_runtime.h>
#include <cuda_bf16.h>
#include <math.h>
#include <cstdint>

#define Bsz 1024
#define Kn  200
#define Dm  128
#define D2  256
#define G8  1024

typedef __nv_bfloat16 bf16;

__device__ __forceinline__ void split2(float x, bf16& h, bf16& l) {
    h = __float2bfloat16(x);
    l = __float2bfloat16(x - __bfloat162float(h));
}
__device__ __forceinline__ uint32_t pk2(bf16 a, bf16 b) {
    uint16_t ua = *(uint16_t*)&a, ub = *(uint16_t*)&b;
    return (uint32_t)ua | ((uint32_t)ub << 16);
}
__device__ __forceinline__ void splitp(float x0, float x1, uint32_t& hp, uint32_t& lp) {
    bf16 h0, l0, h1, l1;
    split2(x0, h0, l0); split2(x1, h1, l1);
    hp = pk2(h0, h1); lp = pk2(l0, l1);
}

__device__ __forceinline__ void mma16816(float* c, const uint32_t* a, const uint32_t* b) {
    asm volatile(
        "mma.sync.aligned.m16n8k16.row.col.f32.bf16.bf16.f32 "
        "{%0,%1,%2,%3}, {%4,%5,%6,%7}, {%8,%9}, {%0,%1,%2,%3};"
        : "+f"(c[0]), "+f"(c[1]), "+f"(c[2]), "+f"(c[3])
        : "r"(a[0]), "r"(a[1]), "r"(a[2]), "r"(a[3]), "r"(b[0]), "r"(b[1]));
}

// ================= scratch =================
__device__ float g_qe[Bsz * Dm];
__device__ float g_sup[Bsz * Dm];
__device__ float g_sg[Bsz * Dm];
__device__ float g_sgn2[Bsz];
__device__ float g_qWb[Bsz * G8];
__device__ float g_scores[Bsz * Bsz];
__device__ float g_c[Bsz * D2];
__device__ float g_hout[Bsz * Dm];
__device__ float g_rp[8 * Bsz * Dm];
__device__ float g_bperm[G8];

__device__ bf16 g_scatA[Bsz * 768];
__device__ bf16 g_qeA[Bsz * 384];
__device__ bf16 g_supA[Bsz * 384];
__device__ bf16 g_hidA[Bsz * 768];
__device__ bf16 g_houtA[Bsz * 384];
__device__ bf16 g_hrA[Bsz * 768];
__device__ bf16 g_P[Bsz * 3072];
__device__ bf16 g_sgB[Bsz * 384];
__device__ bf16 g_sgT[Dm * 3072];
__device__ bf16 g_gcnB[Dm * 768];
__device__ bf16 g_p1B[D2 * 384];
__device__ bf16 g_p2B[Dm * 768];
__device__ bf16 g_wihB[G8 * 384];
__device__ bf16 g_whhB[G8 * 768];

// ================= fused front: weight conversion + gather-sum =================
__device__ __forceinline__ void convB_row(const float* src, bf16* dst, int srow,
                                          int drow, int K, int j) {
    if (j < K) {
        bf16 h, l; split2(src[(size_t)srow * K + j], h, l);
        bf16* d = dst + (size_t)drow * 3 * K;
        d[j] = h; d[K + j] = l; d[2 * K + j] = h;
    }
}
__global__ void front_kernel(const float* __restrict__ gcn_w, const float* __restrict__ p1_w,
                             const float* __restrict__ p2_w, const float* __restrict__ w_ih,
                             const float* __restrict__ w_hh, const float* __restrict__ b_ih,
                             const float* __restrict__ b_hh,
                             const int* __restrict__ rel, const int* __restrict__ ent,
                             const int* __restrict__ query, const float* __restrict__ emb) {
    int blk = blockIdx.x, j = threadIdx.x;
    if (blk < 128) {
        convB_row(gcn_w, g_gcnB, blk, blk, 256, j);
    } else if (blk < 384) {
        convB_row(p1_w, g_p1B, blk - 128, blk - 128, 128, j);
    } else if (blk < 512) {
        convB_row(p2_w, g_p2B, blk - 384, blk - 384, 256, j);
    } else if (blk < 1536) {
        int n = blk - 512;
        convB_row(w_ih, g_wihB, n, (n & 255) * 4 + (n >> 8), 128, j);
    } else if (blk < 2560) {
        int n = blk - 1536;
        convB_row(w_hh, g_whhB, n, (n & 255) * 4 + (n >> 8), 256, j);
    } else if (blk == 2560) {
        #pragma unroll
        for (int gidx = 0; gidx < 4; gidx++) {
            int n = gidx * 256 + j;
            g_bperm[j * 4 + gidx] = b_ih[n] + b_hh[n];
        }
    } else {
        __shared__ int sidx[2 * Kn];
        int b = blk - 2561;
        int half = j >> 7;          // 0 rel, 1 ent
        int d = j & 127;
        if (half == 0) {
            for (int i = d; i < Kn; i += 128) sidx[i] = rel[b * Kn + i];
        } else {
            for (int i = d; i < Kn; i += 128) sidx[Kn + i] = ent[b * Kn + i];
        }
        __syncthreads();
        const int* idx = sidx + half * Kn;
        float a = 0.f;
        #pragma unroll 8
        for (int k = 0; k < Kn; k++) a += __ldg(&emb[(size_t)idx[k] * Dm + d]);
        bf16 h, l;
        bf16* sa = g_scatA + (size_t)b * 768;
        split2(a, h, l);
        if (half == 0) { sa[d] = h; sa[256 + d] = h; sa[512 + d] = l; }
        else           { sa[128 + d] = h; sa[384 + d] = h; sa[640 + d] = l; }
        if (half == 0) {
            float qv = emb[(size_t)query[b] * Dm + d];
            g_qe[b * Dm + d] = qv;
            bf16* qa = g_qeA + (size_t)b * 384;
            split2(qv, h, l); qa[d] = h; qa[128 + d] = h; qa[256 + d] = l;
        }
    }
}

// ================= fused FFN: sup -> hid -> z+LN, row-local per CTA ============
// 64 CTAs x 16 rows, 256 threads. Weights streamed through double-buffered smem;
// activations resident in smem. Outputs: g_sg, g_sgB, g_sgn2.
#define BST 136
#define OFF_A1 0                       // scatA tile 16 x 776
#define OFF_A2 12416                   // supA 16 x 392
#define OFF_A3 18688                   // hidA 16 x 776
#define OFF_BB 31104                   // B double buffer 2 x 128 x 136
#define OFF_SF 65920                   // supF (float) 16 x 132
#define FFN_SMEM ((65920 + 4224) * 2)  // bytes
__global__ __launch_bounds__(256, 1) void ffn_kernel(
    const float* __restrict__ gcn_b, const float* __restrict__ p1_b,
    const float* __restrict__ p2_b, const float* __restrict__ lna,
    const float* __restrict__ lnb) {
    extern __shared__ bf16 sh[];
    float* supF = (float*)(sh + OFF_SF);
    __shared__ float rsum[16], rsq[16], rn2[16];
    int tid = threadIdx.x;
    int wid = tid >> 5, lane = tid & 31;
    int g = lane >> 2, t = lane & 3;
    int wn = wid;
    int R0 = blockIdx.x * 16;

    // load 16 rows of scatA (K=768) into resident smem
    #pragma unroll
    for (int i = 0; i < 6; i++) {
        int li = tid + i * 256;            // 0..1535
        int row = li / 96, cg = li - row * 96;
        uint4 v = *(const uint4*)&g_scatA[(size_t)(R0 + row) * 768 + cg * 8];
        *(uint4*)&sh[OFF_A1 + row * 776 + cg * 8] = v;
    }
    __syncthreads();

    int lr = tid >> 4, lc = (tid & 15) * 8;
    bf16* B0 = sh + OFF_BB;
    bf16* B1 = B0 + 128 * BST;

    // one GEMM pass: A resident (stride ast), B streamed (k3 row stride, nch chunks)
    auto run = [&](const bf16* As, int ast, const bf16* Bg, int k3, int nch,
                   float acc[2][4]) {
        const bf16* Bbase = Bg + (size_t)lr * k3 + lc;
        size_t rs = (size_t)16 * k3;
        uint4 pb[8];
        #pragma unroll
        for (int i = 0; i < 8; i++) pb[i] = *(const uint4*)(Bbase + i * rs);
        #pragma unroll
        for (int i = 0; i < 8; i++) *(uint4*)&B0[(lr + 16 * i) * BST + lc] = pb[i];
        if (nch > 1) {
            #pragma unroll
            for (int i = 0; i < 8; i++) pb[i] = *(const uint4*)(Bbase + i * rs + 128);
        }
        __syncthreads();
        for (int c = 0; c < nch; c++) {
            const bf16* Bs = (c & 1) ? B1 : B0;
            #pragma unroll
            for (int k = 0; k < 8; k++) {
                int col = c * 128 + k * 16 + 2 * t;
                uint32_t a[4], b[2][2];
                a[0] = *(const uint32_t*)&As[g * ast + col];
                a[1] = *(const uint32_t*)&As[(g + 8) * ast + col];
                a[2] = *(const uint32_t*)&As[g * ast + col + 8];
                a[3] = *(const uint32_t*)&As[(g + 8) * ast + col + 8];
                #pragma unroll
                for (int jn = 0; jn < 2; jn++) {
                    int n = wn * 16 + jn * 8 + g;
                    b[jn][0] = *(const uint32_t*)&Bs[n * BST + k * 16 + 2 * t];
                    b[jn][1] = *(const uint32_t*)&Bs[n * BST + k * 16 + 2 * t + 8];
                }
                #pragma unroll
                for (int jn = 0; jn < 2; jn++) mma16816(acc[jn], a, b[jn]);
            }
            if (c + 1 < nch) {
                bf16* Bd = ((c + 1) & 1) ? B1 : B0;
                #pragma unroll
                for (int i = 0; i < 8; i++) *(uint4*)&Bd[(lr + 16 * i) * BST + lc] = pb[i];
                if (c + 2 < nch) {
                    int off = (c + 2) * 128;
                    #pragma unroll
                    for (int i = 0; i < 8; i++) pb[i] = *(const uint4*)(Bbase + i * rs + off);
                }
                __syncthreads();
            }
        }
    };

    // ---- stage 1: sup = tanh((scat @ gcn^T + 200 b)/1024) ----
    {
        float acc[2][4] = {};
        run(sh + OFF_A1, 776, g_gcnB, 768, 6, acc);
        #pragma unroll
        for (int jn = 0; jn < 2; jn++) {
            int cb = wn * 16 + jn * 8 + 2 * t;
            float bb0 = 200.0f * __ldg(&gcn_b[cb]), bb1 = 200.0f * __ldg(&gcn_b[cb + 1]);
            #pragma unroll
            for (int pr = 0; pr < 2; pr++) {
                int row = g + pr * 8;
                float v0 = tanhf((acc[jn][2 * pr] + bb0) * (1.0f / 1024.0f));
                float v1 = tanhf((acc[jn][2 * pr + 1] + bb1) * (1.0f / 1024.0f));
                supF[row * 132 + cb] = v0;
                supF[row * 132 + cb + 1] = v1;
                uint32_t hp, lp; splitp(v0, v1, hp, lp);
                bf16* sa = sh + OFF_A2 + row * 392;
                *(uint32_t*)&sa[cb] = hp;
                *(uint32_t*)&sa[128 + cb] = hp;
                *(uint32_t*)&sa[256 + cb] = lp;
            }
        }
        __syncthreads();
    }

    // ---- stage 2: hid = relu(sup @ p1^T + b), N=256 in two 128 passes ----
    for (int nb = 0; nb < 2; nb++) {
        float acc[2][4] = {};
        run(sh + OFF_A2, 392, g_p1B + (size_t)nb * 128 * 384, 384, 3, acc);
        #pragma unroll
        for (int jn = 0; jn < 2; jn++) {
            int cbg = nb * 128 + wn * 16 + jn * 8 + 2 * t;
            float bb0 = __ldg(&p1_b[cbg]), bb1 = __ldg(&p1_b[cbg + 1]);
            #pragma unroll
            for (int pr = 0; pr < 2; pr++) {
                int row = g + pr * 8;
                float v0 = fmaxf(acc[jn][2 * pr] + bb0, 0.0f);
                float v1 = fmaxf(acc[jn][2 * pr + 1] + bb1, 0.0f);
                uint32_t hp, lp; splitp(v0, v1, hp, lp);
                bf16* ha = sh + OFF_A3 + row * 776;
                *(uint32_t*)&ha[cbg] = hp;
                *(uint32_t*)&ha[256 + cbg] = hp;
                *(uint32_t*)&ha[512 + cbg] = lp;
            }
        }
        __syncthreads();
    }

    // ---- stage 3: z = hid @ p2^T + b + sup; layernorm ----
    if (tid < 16) { rsum[tid] = 0.f; rsq[tid] = 0.f; rn2[tid] = 0.f; }
    __syncthreads();
    {
        float acc[2][4] = {};
        run(sh + OFF_A3, 776, g_p2B, 768, 6, acc);
        float s0 = 0.f, s1 = 0.f, q0 = 0.f, q1 = 0.f;
        #pragma unroll
        for (int jn = 0; jn < 2; jn++) {
            int cb = wn * 16 + jn * 8 + 2 * t;
            float bb0 = __ldg(&p2_b[cb]), bb1 = __ldg(&p2_b[cb + 1]);
            float z0 = acc[jn][0] + bb0 + supF[g * 132 + cb];
            float z1 = acc[jn][1] + bb1 + supF[g * 132 + cb + 1];
            float z2 = acc[jn][2] + bb0 + supF[(g + 8) * 132 + cb];
            float z3 = acc[jn][3] + bb1 + supF[(g + 8) * 132 + cb + 1];
            acc[jn][0] = z0; acc[jn][1] = z1; acc[jn][2] = z2; acc[jn][3] = z3;
            s0 += z0 + z1; q0 += z0 * z0 + z1 * z1;
            s1 += z2 + z3; q1 += z2 * z2 + z3 * z3;
        }
        atomicAdd(&rsum[g], s0); atomicAdd(&rsq[g], q0);
        atomicAdd(&rsum[g + 8], s1); atomicAdd(&rsq[g + 8], q1);
        __syncthreads();
        float mu0 = rsum[g] * (1.0f / 128.0f);
        float mu1 = rsum[g + 8] * (1.0f / 128.0f);
        float sd0 = sqrtf(fmaxf((rsq[g] - 128.0f * mu0 * mu0) * (1.0f / 127.0f), 0.f)) + 1e-3f;
        float sd1 = sqrtf(fmaxf((rsq[g + 8] - 128.0f * mu1 * mu1) * (1.0f / 127.0f), 0.f)) + 1e-3f;
        float i0 = 1.0f / sd0, i1 = 1.0f / sd1;
        float n20 = 0.f, n21 = 0.f;
        #pragma unroll
        for (int jn = 0; jn < 2; jn++) {
            int cb = wn * 16 + jn * 8 + 2 * t;
            float la0 = __ldg(&lna[cb]), la1 = __ldg(&lna[cb + 1]);
            float lb0 = __ldg(&lnb[cb]), lb1 = __ldg(&lnb[cb + 1]);
            float sg0 = (acc[jn][0] - mu0) * i0 * la0 + lb0;
            float sg1 = (acc[jn][1] - mu0) * i0 * la1 + lb1;
            float sg2 = (acc[jn][2] - mu1) * i1 * la0 + lb0;
            float sg3 = (acc[jn][3] - mu1) * i1 * la1 + lb1;
            acc[jn][0] = sg0; acc[jn][1] = sg1; acc[jn][2] = sg2; acc[jn][3] = sg3;
            n20 += sg0 * sg0 + sg1 * sg1;
            n21 += sg2 * sg2 + sg3 * sg3;
        }
        atomicAdd(&rn2[g], n20); atomicAdd(&rn2[g + 8], n21);
        __syncthreads();
        #pragma unroll
        for (int jn = 0; jn < 2; jn++) {
            int cb = wn * 16 + jn * 8 + 2 * t;
            #pragma unroll
            for (int pr = 0; pr < 2; pr++) {
                int row = R0 + g + pr * 8;
                float v0 = acc[jn][2 * pr], v1 = acc[jn][2 * pr + 1];
                *(float2*)&g_sg[row * Dm + cb] = make_float2(v0, v1);
                uint32_t hp, lp; splitp(v0, v1, hp, lp);
                bf16* sb = g_sgB + (size_t)row * 384;
                *(uint32_t*)&sb[cb] = hp;
                *(uint32_t*)&sb[128 + cb] = lp;
                *(uint32_t*)&sb[256 + cb] = hp;
            }
        }
        if (wn == 0 && t == 0) {
            g_sgn2[R0 + g] = rn2[g];
            g_sgn2[R0 + g + 8] = rn2[g + 8];
        }
    }
}

// ================= bf16 mma GEMM, CTA tile MTx128, BK=128, double-buffered =====
// MODE: 0 store; 4 QWB+LSTM1; 6 HH+LSTM  (only MT=64 instantiated)
#define SMS 136
template <int MODE, int MT>
__global__ __launch_bounds__(256, (MT <= 32) ? 2 : 1)
void gemm_tc(const bf16* __restrict__ A, const bf16* __restrict__ B,
             float* __restrict__ C, int N, int K3, int klen,
             const float* __restrict__ b0, const float* __restrict__ b1,
             const float* __restrict__ b2) {
    constexpr int IM = MT / 16;
    constexpr int STG = (MT + 128) * SMS;
    extern __shared__ bf16 sm[];
    int tid = threadIdx.x;
    int wid = tid >> 5, lane = tid & 31;
    int g = lane >> 2, t = lane & 3;
    int wn = wid;
    int nblk = blockIdx.x, mblk = blockIdx.y;
    int koff = blockIdx.z * klen;
    const bf16* Ab = A + (size_t)(mblk * MT) * K3 + koff;
    const bf16* Bb = B + (size_t)(nblk * 128) * K3 + koff;

    float acc[IM][2][4];
    #pragma unroll
    for (int i = 0; i < IM; i++)
        #pragma unroll
        for (int j = 0; j < 2; j++)
            #pragma unroll
            for (int q = 0; q < 4; q++) acc[i][j][q] = 0.f;

    int lr = tid >> 4;
    int lc = (tid & 15) * 8;
    int nch = klen >> 7;
    const bf16* Abase = Ab + (size_t)lr * K3 + lc;
    const bf16* Bbase = Bb + (size_t)lr * K3 + lc;
    size_t rs = (size_t)16 * K3;

    uint4 pa[IM], pb[8];
    #pragma unroll
    for (int i = 0; i < IM; i++) pa[i] = *(const uint4*)(Abase + i * rs);
    #pragma unroll
    for (int i = 0; i < 8; i++) pb[i] = *(const uint4*)(Bbase + i * rs);
    {
        bf16* Sd = sm;
        #pragma unroll
        for (int i = 0; i < IM; i++) *(uint4*)&Sd[(lr + 16 * i) * SMS + lc] = pa[i];
        bf16* Bd = sm + MT * SMS;
        #pragma unroll
        for (int i = 0; i < 8; i++) *(uint4*)&Bd[(lr + 16 * i) * SMS + lc] = pb[i];
    }
    if (nch > 1) {
        #pragma unroll
        for (int i = 0; i < IM; i++) pa[i] = *(const uint4*)(Abase + i * rs + 128);
        #pragma unroll
        for (int i = 0; i < 8; i++) pb[i] = *(const uint4*)(Bbase + i * rs + 128);
    }
    __syncthreads();

    for (int c = 0; c < nch; c++) {
        const bf16* As = sm + (c & 1) * STG;
        const bf16* Bs = As + MT * SMS;
        #pragma unroll
        for (int k = 0; k < 8; k++) {
            uint32_t a[IM][4], b[2][2];
            #pragma unroll
            for (int im = 0; im < IM; im++) {
                int r = im * 16 + g;
                a[im][0] = *(const uint32_t*)&As[r * SMS + k * 16 + 2 * t];
                a[im][1] = *(const uint32_t*)&As[(r + 8) * SMS + k * 16 + 2 * t];
                a[im][2] = *(const uint32_t*)&As[r * SMS + k * 16 + 2 * t + 8];
                a[im][3] = *(const uint32_t*)&As[(r + 8) * SMS + k * 16 + 2 * t + 8];
            }
            #pragma unroll
            for (int jn = 0; jn < 2; jn++) {
                int n = wn * 16 + jn * 8 + g;
                b[jn][0] = *(const uint32_t*)&Bs[n * SMS + k * 16 + 2 * t];
                b[jn][1] = *(const uint32_t*)&Bs[n * SMS + k * 16 + 2 * t + 8];
            }
            #pragma unroll
            for (int im = 0; im < IM; im++)
                #pragma unroll
                for (int jn = 0; jn < 2; jn++)
                    mma16816(acc[im][jn], a[im], b[jn]);
        }
        if (c + 1 < nch) {
            bf16* Sd = sm + ((c + 1) & 1) * STG;
            #pragma unroll
            for (int i = 0; i < IM; i++) *(uint4*)&Sd[(lr + 16 * i) * SMS + lc] = pa[i];
            bf16* Bd = Sd + MT * SMS;
            #pragma unroll
            for (int i = 0; i < 8; i++) *(uint4*)&Bd[(lr + 16 * i) * SMS + lc] = pb[i];
            if (c + 2 < nch) {
                int off = (c + 2) * 128;
                #pragma unroll
                for (int i = 0; i < IM; i++) pa[i] = *(const uint4*)(Abase + i * rs + off);
                #pragma unroll
                for (int i = 0; i < 8; i++) pb[i] = *(const uint4*)(Bbase + i * rs + off);
            }
            __syncthreads();
        }
    }

    // ---------------- epilogues ----------------
    if constexpr (MODE == 0) {
        float* Cz = C + (size_t)blockIdx.z * 1024 * N;
        #pragma unroll
        for (int im = 0; im < IM; im++)
            #pragma unroll
            for (int jn = 0; jn < 2; jn++) {
                int r0 = mblk * MT + im * 16 + g;
                int cb = nblk * 128 + wn * 16 + jn * 8 + 2 * t;
                *(float2*)&Cz[(size_t)r0 * N + cb] = make_float2(acc[im][jn][0], acc[im][jn][1]);
                *(float2*)&Cz[(size_t)(r0 + 8) * N + cb] = make_float2(acc[im][jn][2], acc[im][jn][3]);
            }
    } else {
        constexpr int first = (MODE == 4);
        #pragma unroll
        for (int im = 0; im < IM; im++)
            #pragma unroll
            for (int jn = 0; jn < 2; jn++) {
                int r0 = mblk * MT + im * 16 + g;
                int base8 = nblk * 128 + wn * 16 + jn * 8;
                int cb = base8 + 2 * t;
                float v0 = acc[im][jn][0], v1 = acc[im][jn][1];
                float v2 = acc[im][jn][2], v3 = acc[im][jn][3];
                if constexpr (first) {
                    float bb0 = __ldg(&g_bperm[cb]), bb1 = __ldg(&g_bperm[cb + 1]);
                    v0 += bb0; v1 += bb1; v2 += bb0; v3 += bb1;
                    *(float2*)&g_qWb[(size_t)r0 * G8 + cb] = make_float2(v0, v1);
                    *(float2*)&g_qWb[(size_t)(r0 + 8) * G8 + cb] = make_float2(v2, v3);
                } else {
                    float2 a0 = *(const float2*)&g_qWb[(size_t)r0 * G8 + cb];
                    float2 a1 = *(const float2*)&g_qWb[(size_t)(r0 + 8) * G8 + cb];
                    v0 += a0.x; v1 += a0.y; v2 += a1.x; v3 += a1.y;
                }
                float ex0 = __shfl_xor_sync(0xffffffffu, v0, 1);
                float ex1 = __shfl_xor_sync(0xffffffffu, v1, 1);
                float ex2 = __shfl_xor_sync(0xffffffffu, v2, 1);
                float ex3 = __shfl_xor_sync(0xffffffffu, v3, 1);
                float gi, gf, gg, go; int row;
                if ((t & 1) == 0) { gi = v0; gf = v1; gg = ex0; go = ex1; row = r0; }
                else             { gi = ex2; gf = ex3; gg = v2; go = v3; row = r0 + 8; }
                int j = (base8 >> 2) + (t >> 1);
                float cp = first ? 0.0f : g_c[row * D2 + j];
                float si = 1.0f / (1.0f + __expf(-gi));
                float sf = 1.0f / (1.0f + __expf(-gf));
                float so = 1.0f / (1.0f + __expf(-go));
                float cc = sf * cp + si * tanhf(gg);
                g_c[row * D2 + j] = cc;
                float h = so * tanhf(cc);
                if (j < Dm) {
                    float ho = g_qe[row * Dm + j] + h;
                    g_hout[row * Dm + j] = ho;
                    bf16 hh2, ll2; split2(ho, hh2, ll2);
                    bf16* ha = g_houtA + (size_t)row * 384;
                    ha[j] = hh2; ha[128 + j] = hh2; ha[256 + j] = ll2;
                    bf16* ra2 = g_hrA + (size_t)row * 768;
                    ra2[j] = hh2; ra2[256 + j] = hh2; ra2[512 + j] = ll2;
                }
            }
    }
}

// ================= sgT transpose =================
#define SGT_SMEM (128 * 129 * 4)
__global__ __launch_bounds__(256, 1) void sgt_kernel() {
    extern __shared__ float sf[];
    int tid = threadIdx.x;
    int grp = blockIdx.x;
    #pragma unroll
    for (int i = 0; i < 16; i++) {
        int li = tid + i * 256;
        int row = li >> 5;
        int c4 = (li & 31) * 4;
        float4 v = *(const float4*)&g_sg[(size_t)(grp * 128 + row) * Dm + c4];
        float* dst = &sf[row * 129 + c4];
        dst[0] = v.x; dst[1] = v.y; dst[2] = v.z; dst[3] = v.w;
    }
    __syncthreads();
    int d = tid >> 1, half = tid & 1;
    bf16* base = g_sgT + (size_t)d * 3072 + grp * 384;
    for (int bb = 0; bb < 8; bb++) {
        int b0 = half * 64 + bb * 8;
        uint32_t hp[4], lp[4];
        #pragma unroll
        for (int q = 0; q < 4; q++) {
            float x0 = sf[(b0 + 2 * q) * 129 + d];
            float x1 = sf[(b0 + 2 * q + 1) * 129 + d];
            splitp(x0, x1, hp[q], lp[q]);
        }
        uint4 h4 = make_uint4(hp[0], hp[1], hp[2], hp[3]);
        uint4 l4 = make_uint4(lp[0], lp[1], lp[2], lp[3]);
        *(uint4*)&base[b0] = h4;
        *(uint4*)&base[128 + b0] = l4;
        *(uint4*)&base[256 + b0] = h4;
    }
}

// ================= softmax / reduce / cosine =================
__global__ void softmax_kernel() {
    __shared__ float s[8];
    int b = blockIdx.x, t = threadIdx.x;
    const float4* row = (const float4*)(g_scores + (size_t)b * Bsz);
    float4 x = row[t];
    float m = fmaxf(fmaxf(x.x, x.y), fmaxf(x.z, x.w));
    #pragma unroll
    for (int o = 16; o; o >>= 1) m = fmaxf(m, __shfl_xor_sync(0xffffffffu, m, o));
    if ((t & 31) == 0) s[t >> 5] = m;
    __syncthreads();
    m = fmaxf(fmaxf(fmaxf(s[0], s[1]), fmaxf(s[2], s[3])),
              fmaxf(fmaxf(s[4], s[5]), fmaxf(s[6], s[7])));
    __syncthreads();
    float e0 = __expf(x.x - m), e1 = __expf(x.y - m);
    float e2 = __expf(x.z - m), e3 = __expf(x.w - m);
    float l = e0 + e1 + e2 + e3;
    #pragma unroll
    for (int o = 16; o; o >>= 1) l += __shfl_xor_sync(0xffffffffu, l, o);
    if ((t & 31) == 0) s[t >> 5] = l;
    __syncthreads();
    l = s[0] + s[1] + s[2] + s[3] + s[4] + s[5] + s[6] + s[7];
    float inv = 1.0f / l;
    float p0 = e0 * inv, p1 = e1 * inv, p2 = e2 * inv, p3 = e3 * inv;
    int j0 = t * 4;
    int ks = j0 >> 7, jl0 = j0 & 127;
    bf16* base = g_P + (size_t)b * 3072 + ks * 384 + jl0;
    uint32_t hp0, lp0, hp1, lp1;
    splitp(p0, p1, hp0, lp0);
    splitp(p2, p3, hp1, lp1);
    ((uint32_t*)base)[0] = hp0; ((uint32_t*)base)[1] = hp1;
    ((uint32_t*)(base + 128))[0] = hp0; ((uint32_t*)(base + 128))[1] = hp1;
    ((uint32_t*)(base + 256))[0] = lp0; ((uint32_t*)(base + 256))[1] = lp1;
}

__global__ void reduce_r_kernel() {
    int b = blockIdx.x, d = threadIdx.x;
    float r = 0.f;
    #pragma unroll
    for (int z = 0; z < 8; z++) r += g_rp[(size_t)z * Bsz * Dm + b * Dm + d];
    bf16 h, l; split2(r, h, l);
    bf16* ra = g_hrA + (size_t)b * 768;
    ra[128 + d] = h; ra[384 + d] = h; ra[640 + d] = l;
}

__global__ void cosine_kernel(float* __restrict__ out) {
    __shared__ float s[4];
    int b = blockIdx.x, d = threadIdx.x;
    float ho = g_hout[b * Dm + d];
    float sg = g_sg[b * Dm + d];
    float cross = ho * sg, n1 = ho * ho;
    #pragma unroll
    for (int o = 16; o; o >>= 1) {
        cross += __shfl_xor_sync(0xffffffffu, cross, o);
        n1 += __shfl_xor_sync(0xffffffffu, n1, o);
    }
    if ((d & 31) == 0) { s[d >> 5] = cross; }
    __syncthreads();
    float cr = s[0] + s[1] + s[2] + s[3];
    __syncthreads();
    if ((d & 31) == 0) { s[d >> 5] = n1; }
    __syncthreads();
    float nn = s[0] + s[1] + s[2] + s[3];
    if (d == 0) out[b] = cr * rsqrtf(nn * g_sgn2[b]);
}

// ================= host orchestration =================
#define SM64 (2 * (192 * SMS) * 2)
extern "C" void kernel_launch(void* const* d_in, const int* in_sizes, int n_in,
                              void* d_out, int out_size) {
    (void)in_sizes; (void)n_in; (void)out_size;
    const int*   relations = (const int*)d_in[0];
    const int*   entities  = (const int*)d_in[1];
    const int*   query     = (const int*)d_in[2];
    const float* emb       = (const float*)d_in[3];
    const float* gcn_w     = (const float*)d_in[4];
    const float* gcn_b     = (const float*)d_in[5];
    const float* p1_w      = (const float*)d_in[6];
    const float* p1_b      = (const float*)d_in[7];
    const float* p2_w      = (const float*)d_in[8];
    const float* p2_b      = (const float*)d_in[9];
    const float* ln_a      = (const float*)d_in[10];
    const float* ln_b      = (const float*)d_in[11];
    const float* w_ih      = (const float*)d_in[12];
    const float* w_hh      = (const float*)d_in[13];
    const float* b_ih      = (const float*)d_in[14];
    const float* b_hh      = (const float*)d_in[15];
    float* out = (float*)d_out;

    cudaFuncSetAttribute(gemm_tc<0, 64>, cudaFuncAttributeMaxDynamicSharedMemorySize, SM64);
    cudaFuncSetAttribute(gemm_tc<4, 64>, cudaFuncAttributeMaxDynamicSharedMemorySize, SM64);
    cudaFuncSetAttribute(gemm_tc<6, 64>, cudaFuncAttributeMaxDynamicSharedMemorySize, SM64);
    cudaFuncSetAttribute(ffn_kernel, cudaFuncAttributeMaxDynamicSharedMemorySize, FFN_SMEM);
    cudaFuncSetAttribute(sgt_kernel, cudaFuncAttributeMaxDynamicSharedMemorySize, SGT_SMEM);

    float *scores, *rp;
    bf16 *qeA, *houtA, *hrA, *P, *sgB, *sgT, *wihB, *whhB;
    cudaGetSymbolAddress((void**)&scores, g_scores);
    cudaGetSymbolAddress((void**)&rp, g_rp);
    cudaGetSymbolAddress((void**)&qeA, g_qeA);
    cudaGetSymbolAddress((void**)&houtA, g_houtA);
    cudaGetSymbolAddress((void**)&hrA, g_hrA);
    cudaGetSymbolAddress((void**)&P, g_P);
    cudaGetSymbolAddress((void**)&sgB, g_sgB);
    cudaGetSymbolAddress((void**)&sgT, g_sgT);
    cudaGetSymbolAddress((void**)&wihB, g_wihB);
    cudaGetSymbolAddress((void**)&whhB, g_whhB);

    // 1) fused weight conversions + bias permutation + gather-sum
    front_kernel<<<2561 + Bsz, 256>>>(gcn_w, p1_w, p2_w, w_ih, w_hh, b_ih, b_hh,
                                      relations, entities, query, emb);
    // 2) fused FFN chain: sup -> hid -> z + layernorm
    ffn_kernel<<<64, 256, FFN_SMEM>>>(gcn_b, p1_b, p2_b, ln_a, ln_b);
    // 3) sgT transpose
    sgt_kernel<<<8, 256, SGT_SMEM>>>();
    // 4) qWb + first LSTM step
    gemm_tc<4, 64><<<dim3(8, 16), 256, SM64>>>(qeA, wihB, nullptr, G8, 384, 384,
                                               nullptr, nullptr, nullptr);
    // 5) 3 attention+LSTM iterations
    for (int s = 1; s < 4; s++) {
        gemm_tc<0, 64><<<dim3(8, 16), 256, SM64>>>(houtA, sgB, scores, Bsz, 384, 384,
                                                   nullptr, nullptr, nullptr);
        softmax_kernel<<<Bsz, 256>>>();
        gemm_tc<0, 64><<<dim3(1, 16, 8), 256, SM64>>>(P, sgT, rp, Dm, 3072, 384,
                                                      nullptr, nullptr, nullptr);
        reduce_r_kernel<<<Bsz, Dm>>>();
        gemm_tc<6, 64><<<dim3(8, 16), 256, SM64>>>(hrA, whhB, nullptr, G8, 768, 768,
                                                   nullptr, nullptr, nullptr);
    }
    // 6) cosine
    cosine_kernel<<<Bsz, Dm>>>(out);
}